// round 11
// baseline (speedup 1.0000x reference)
#include <cuda_runtime.h>
#include <cuda_fp16.h>
#include <cstdint>
#include <math.h>

// ---------------- problem constants ----------------
#define N_TOK 4096
#define DIM   1024
#define FF    4096
#define NE    8
#define TEMP  0.9f
#define EPS   1e-5f
#define PADMAX 9216

// ---------------- static device scratch ----------------
__device__ __half g_Xe[(size_t)PADMAX * DIM];    // fp16 gathered X
__device__ __half g_H [(size_t)PADMAX * FF];     // fp16 gelu acts
__device__ float  g_Y [(size_t)PADMAX * DIM];    // fp32 expert outputs
__device__ __half g_w1h[(size_t)NE * DIM * FF];  // fp16 w1
__device__ __half g_w2h[(size_t)NE * FF * DIM];  // fp16 w2
__device__ int   g_e0[N_TOK], g_e1[N_TOK];
__device__ float g_p0[N_TOK], g_p1[N_TOK];
__device__ int   g_pp0[N_TOK], g_pp1[N_TOK];
__device__ int   g_counts[NE], g_poff[NE], g_cursor[NE];
__device__ int   g_rowtok[PADMAX];

// ---------------- helpers ----------------
__device__ __forceinline__ uint32_t smem_u32(const void* p) {
    uint32_t a;
    asm("{ .reg .u64 t; cvta.to.shared.u64 t, %1; cvt.u32.u64 %0, t; }" : "=r"(a) : "l"(p));
    return a;
}
__device__ __forceinline__ void cp_async16(uint32_t dst, const void* src) {
    asm volatile("cp.async.cg.shared.global [%0], [%1], 16;" :: "r"(dst), "l"(src));
}
__device__ __forceinline__ uint32_t pack_f16x2(float lo, float hi) {
    uint32_t d;
    asm("cvt.rn.f16x2.f32 %0, %1, %2;" : "=r"(d) : "f"(hi), "f"(lo));
    return d;
}
__device__ __forceinline__ void ldmx4(uint32_t* r, uint32_t addr) {
    asm volatile("ldmatrix.sync.aligned.m8n8.x4.shared.b16 {%0,%1,%2,%3}, [%4];"
        : "=r"(r[0]), "=r"(r[1]), "=r"(r[2]), "=r"(r[3]) : "r"(addr));
}
__device__ __forceinline__ void ldmx4_t(uint32_t* r, uint32_t addr) {
    asm volatile("ldmatrix.sync.aligned.m8n8.x4.trans.shared.b16 {%0,%1,%2,%3}, [%4];"
        : "=r"(r[0]), "=r"(r[1]), "=r"(r[2]), "=r"(r[3]) : "r"(addr));
}
__device__ __forceinline__ void mma_f16(float* c, const uint32_t* a, const uint32_t* b) {
    asm volatile(
        "mma.sync.aligned.m16n8k16.row.col.f32.f16.f16.f32 "
        "{%0,%1,%2,%3}, {%4,%5,%6,%7}, {%8,%9}, {%0,%1,%2,%3};"
        : "+f"(c[0]), "+f"(c[1]), "+f"(c[2]), "+f"(c[3])
        : "r"(a[0]), "r"(a[1]), "r"(a[2]), "r"(a[3]), "r"(b[0]), "r"(b[1]));
}
__device__ __forceinline__ float warp_sum(float v) {
#pragma unroll
    for (int o = 16; o > 0; o >>= 1) v += __shfl_xor_sync(0xffffffffu, v, o);
    return v;
}

// ---------------- weight fp16 pre-conversion (split per weight) ----------------
template<bool W1>
__global__ __launch_bounds__(256)
void convw_kernel(const float* __restrict__ w) {
    const size_t total4 = (size_t)NE * DIM * FF / 4;
    size_t i = (size_t)blockIdx.x * 256 + threadIdx.x;
    const float4* s = reinterpret_cast<const float4*>(w);
    uint2* d = reinterpret_cast<uint2*>(W1 ? g_w1h : g_w2h);
    for (size_t j = i; j < total4; j += (size_t)gridDim.x * 256) {
        float4 v = s[j];
        d[j] = make_uint2(pack_f16x2(v.x, v.y), pack_f16x2(v.z, v.w));
    }
}

// ---------------- small kernels ----------------
__global__ void zero_kernel() {
    if (threadIdx.x < NE) g_counts[threadIdx.x] = 0;
}

__global__ void gate_kernel(const float* __restrict__ x,
                            const float* __restrict__ gw,
                            const float* __restrict__ gb) {
    int warp = threadIdx.x >> 5, lane = threadIdx.x & 31;
    int t = blockIdx.x * 4 + warp;
    if (t >= N_TOK) return;
    float acc[NE];
#pragma unroll
    for (int e = 0; e < NE; e++) acc[e] = 0.f;
    const float* xr = x + (size_t)t * DIM;
    for (int d = lane; d < DIM; d += 32) {
        float xv = xr[d];
        const float4* g4 = reinterpret_cast<const float4*>(gw + (size_t)d * NE);
        float4 a = g4[0], b = g4[1];
        acc[0] += xv * a.x; acc[1] += xv * a.y; acc[2] += xv * a.z; acc[3] += xv * a.w;
        acc[4] += xv * b.x; acc[5] += xv * b.y; acc[6] += xv * b.z; acc[7] += xv * b.w;
    }
#pragma unroll
    for (int e = 0; e < NE; e++) acc[e] = warp_sum(acc[e]);
    if (lane == 0) {
        float lg[NE];
#pragma unroll
        for (int e = 0; e < NE; e++) lg[e] = (acc[e] + gb[e]) / TEMP;
        int i0 = 0;
#pragma unroll
        for (int e = 1; e < NE; e++) if (lg[e] > lg[i0]) i0 = e;
        int i1 = (i0 == 0) ? 1 : 0;
#pragma unroll
        for (int e = 0; e < NE; e++)
            if (e != i0 && lg[e] > lg[i1]) i1 = e;
        float ev = expf(lg[i1] - lg[i0]);
        float s = 1.f + ev;
        g_e0[t] = i0; g_e1[t] = i1;
        g_p0[t] = 1.f / s; g_p1[t] = ev / s;
        atomicAdd(&g_counts[i0], 1);
        atomicAdd(&g_counts[i1], 1);
    }
}

__global__ void prefix_kernel() {
    if (threadIdx.x == 0) {
        int s = 0;
        for (int e = 0; e < NE; e++) {
            g_poff[e] = s;
            s += ((g_counts[e] + 127) / 128) * 128;
            g_cursor[e] = 0;
        }
    }
}

__global__ void assign_kernel() {
    int t = blockIdx.x * 256 + threadIdx.x;
    if (t >= N_TOK) return;
    int e0 = g_e0[t], e1 = g_e1[t];
    int p = g_poff[e0] + atomicAdd(&g_cursor[e0], 1);
    g_rowtok[p] = t; g_pp0[t] = p;
    int q = g_poff[e1] + atomicAdd(&g_cursor[e1], 1);
    g_rowtok[q] = t; g_pp1[t] = q;
}

// gather + fp16-convert selected token rows into padded per-expert slabs
__global__ void gather_kernel(const float* __restrict__ x) {
    int e  = blockIdx.y;
    int mt = blockIdx.x;
    int cnt = g_counts[e];
    if (mt * 128 >= cnt) return;
    int base = g_poff[e] + mt * 128;
    int tid = threadIdx.x;
    const float4* x4 = reinterpret_cast<const float4*>(x);
    uint2* o2 = reinterpret_cast<uint2*>(g_Xe);
#pragma unroll 4
    for (int i = 0; i < 128; i++) {
        if (mt * 128 + i < cnt) {
            int tok = g_rowtok[base + i];
            float4 v = x4[(size_t)tok * (DIM / 4) + tid];
            o2[(size_t)(base + i) * (DIM / 4) + tid] =
                make_uint2(pack_f16x2(v.x, v.y), pack_f16x2(v.z, v.w));
        }
    }
}

// ---------------- fp16 mma.sync GEMM (all-fp16 operands, ldmatrix) ----------------
// CTA tile 128xBN, BK=32, 4-stage cp.async pipeline, one sync per K-chunk.
// 256 threads = 8 warps (2m x 4n), warp tile 64 x BN/4, mma m16n8k16.
#define STAGES 4
#define A_STRH 40
#define A_STGH (128 * A_STRH)              // halfs per stage
template<int BN> struct BC { static const int STRH = BN + 8; static const int STGH = 32 * (BN + 8); };
#define SMEM_G1 (STAGES * (A_STGH + BC<256>::STGH) * 2)
#define SMEM_G2 (STAGES * (A_STGH + BC<128>::STGH) * 2)

template<int K, int NF, int BN, bool GELU>
__global__ __launch_bounds__(256, (BN == 128 ? 2 : 1))
void ffn_mma_kernel(const float* __restrict__ bias_in) {
    constexpr int BSTRH = BN + 8;
    constexpr int BSTGH = 32 * BSTRH;
    constexpr int WN    = BN / 4;
    constexpr int NFR   = WN / 8;

    int e = blockIdx.z;
    int cnt = g_counts[e];
    int mt = blockIdx.y;
    if (mt * 128 >= cnt) return;
    int m0 = g_poff[e] + mt * 128;
    int n0 = blockIdx.x * BN;

    const __half* Abase = (GELU ? g_Xe : g_H) + (size_t)m0 * K;
    const __half* Bbase = (GELU ? g_w1h : g_w2h) + (size_t)e * K * NF + n0;
    const float*  bias  = bias_in + (size_t)e * NF + n0;

    extern __shared__ __half smh[];
    __half* Asm = smh;
    __half* Bsm = smh + STAGES * A_STGH;
    uint32_t sA32 = smem_u32(Asm), sB32 = smem_u32(Bsm);

    int tid = threadIdx.x, wid = tid >> 5, lane = tid & 31;
    int warp_m = wid & 1, warp_n = wid >> 1;
    int group = lane >> 2, tig = lane & 3;
    int rw = lane & 7, quad = lane >> 3;

    auto load_stage = [&](int kt, int s) {
        int k0 = kt * 32;
        uint32_t aD = sA32 + s * (A_STGH * 2);
        uint32_t bD = sB32 + s * (BSTGH * 2);
#pragma unroll
        for (int i = 0; i < 2; i++) {            // A: 128 rows x 4 x 16B
            int idx = tid + i * 256;
            int row = idx >> 2, c4 = idx & 3;
            cp_async16(aD + row * (A_STRH * 2) + c4 * 16,
                       Abase + (size_t)row * K + k0 + c4 * 8);
        }
#pragma unroll
        for (int i = 0; i < BN / 64; i++) {      // B: 32 rows x BN/8 x 16B
            int idx = tid + i * 256;
            int kk = idx / (BN / 8), c8 = idx % (BN / 8);
            cp_async16(bD + (kk * BSTRH + c8 * 8) * 2,
                       Bbase + (size_t)(k0 + kk) * NF + c8 * 8);
        }
        asm volatile("cp.async.commit_group;");
    };

    float acc[4][NFR][4];
#pragma unroll
    for (int i = 0; i < 4; i++)
#pragma unroll
        for (int j = 0; j < NFR; j++)
#pragma unroll
            for (int q = 0; q < 4; q++) acc[i][j][q] = 0.f;

    const int ktiles = K / 32;
    load_stage(0, 0);
    load_stage(1, 1);
    load_stage(2, 2);

    for (int kt = 0; kt < ktiles; kt++) {
        int rem = ktiles - 1 - kt;
        if (rem >= 2)
            asm volatile("cp.async.wait_group 2;" ::: "memory");
        else if (rem == 1)
            asm volatile("cp.async.wait_group 1;" ::: "memory");
        else
            asm volatile("cp.async.wait_group 0;" ::: "memory");
        __syncthreads();

        if (kt + 3 < ktiles)
            load_stage(kt + 3, (kt + 3) % STAGES);

        int s = kt % STAGES;
        uint32_t aS = sA32 + s * (A_STGH * 2);
        uint32_t bS = sB32 + s * (BSTGH * 2);
#pragma unroll
        for (int ks = 0; ks < 2; ks++) {         // two k16 steps per K32 chunk
            int kb = ks * 16;
            uint32_t a[4][4], b[NFR][2];
#pragma unroll
            for (int m = 0; m < 4; m++) {
                int row = warp_m * 64 + m * 16 + rw + (quad & 1) * 8;
                int col = kb + (quad >> 1) * 8;
                ldmx4(a[m], aS + (row * A_STRH + col) * 2);
            }
#pragma unroll
            for (int n2 = 0; n2 < NFR / 2; n2++) {
                uint32_t r[4];
                int krow = kb + rw + (quad & 1) * 8;
                int col  = warp_n * WN + n2 * 16 + (quad >> 1) * 8;
                ldmx4_t(r, bS + (krow * BSTRH + col) * 2);
                b[2 * n2][0] = r[0]; b[2 * n2][1] = r[1];
                b[2 * n2 + 1][0] = r[2]; b[2 * n2 + 1][1] = r[3];
            }
#pragma unroll
            for (int m = 0; m < 4; m++)
#pragma unroll
                for (int n = 0; n < NFR; n++)
                    mma_f16(acc[m][n], a[m], b[n]);
        }
    }

    // epilogue: bias (+gelu); GEMM1 stores fp16 H, GEMM2 stores fp32 Y
#pragma unroll
    for (int m = 0; m < 4; m++) {
        int r0 = m0 + warp_m * 64 + m * 16 + group;
#pragma unroll
        for (int n = 0; n < NFR; n++) {
            int c = warp_n * WN + n * 8 + tig * 2;
            float bv0 = bias[c], bv1 = bias[c + 1];
#pragma unroll
            for (int h = 0; h < 2; h++) {
                float v0 = acc[m][n][h * 2 + 0] + bv0;
                float v1 = acc[m][n][h * 2 + 1] + bv1;
                if (GELU) {
                    v0 = 0.5f * v0 * (1.f + erff(v0 * 0.70710678118654752f));
                    v1 = 0.5f * v1 * (1.f + erff(v1 * 0.70710678118654752f));
                    *reinterpret_cast<uint32_t*>(
                        g_H + (size_t)(r0 + h * 8) * NF + n0 + c) = pack_f16x2(v0, v1);
                } else {
                    *reinterpret_cast<float2*>(
                        g_Y + (size_t)(r0 + h * 8) * NF + n0 + c) = make_float2(v0, v1);
                }
            }
        }
    }
}

// ---------------- combine + LayerNorm ----------------
__global__ void ln_kernel(const float* __restrict__ ln_g,
                          const float* __restrict__ ln_b,
                          float* __restrict__ out) {
    int t = blockIdx.x;
    __shared__ float sv[DIM];
    __shared__ float rs[8], rq[8];
    int tid = threadIdx.x;
    float p0 = g_p0[t], p1 = g_p1[t];
    const float* ya = g_Y + (size_t)g_pp0[t] * DIM;
    const float* yb = g_Y + (size_t)g_pp1[t] * DIM;
    float lsum = 0.f, lsq = 0.f;
    for (int d = tid; d < DIM; d += 256) {
        float v = p0 * ya[d] + p1 * yb[d];
        sv[d] = v;
        lsum += v; lsq += v * v;
    }
    lsum = warp_sum(lsum); lsq = warp_sum(lsq);
    int lane = tid & 31, wid = tid >> 5;
    if (lane == 0) { rs[wid] = lsum; rq[wid] = lsq; }
    __syncthreads();
    if (tid == 0) {
        float s = 0.f, q = 0.f;
#pragma unroll
        for (int w = 0; w < 8; w++) { s += rs[w]; q += rq[w]; }
        rs[0] = s; rq[0] = q;
    }
    __syncthreads();
    float mu  = rs[0] / DIM;
    float var = rq[0] / DIM - mu * mu;
    float inv = rsqrtf(var + EPS);
    float* outr = out + (size_t)t * DIM;
    for (int d = tid; d < DIM; d += 256)
        outr[d] = (sv[d] - mu) * inv * ln_g[d] + ln_b[d];
}

// ---------------- launch ----------------
extern "C" void kernel_launch(void* const* d_in, const int* in_sizes, int n_in,
                              void* d_out, int out_size) {
    const float* x      = (const float*)d_in[0];
    const float* gate_w = (const float*)d_in[1];
    const float* gate_b = (const float*)d_in[2];
    const float* w1     = (const float*)d_in[3];
    const float* b1     = (const float*)d_in[4];
    const float* w2     = (const float*)d_in[5];
    const float* b2     = (const float*)d_in[6];
    const float* ln_g   = (const float*)d_in[7];
    const float* ln_b   = (const float*)d_in[8];
    float* out = (float*)d_out;

    static cudaStream_t s2 = nullptr;
    static cudaEvent_t ev_fork = nullptr, ev_w1 = nullptr, ev_w2 = nullptr;
    if (s2 == nullptr) {
        cudaStreamCreateWithFlags(&s2, cudaStreamNonBlocking);
        cudaEventCreateWithFlags(&ev_fork, cudaEventDisableTiming);
        cudaEventCreateWithFlags(&ev_w1,   cudaEventDisableTiming);
        cudaEventCreateWithFlags(&ev_w2,   cudaEventDisableTiming);
    }

    cudaFuncSetAttribute(ffn_mma_kernel<DIM, FF, 256, true>,
                         cudaFuncAttributeMaxDynamicSharedMemorySize, SMEM_G1);
    cudaFuncSetAttribute(ffn_mma_kernel<FF, DIM, 128, false>,
                         cudaFuncAttributeMaxDynamicSharedMemorySize, SMEM_G2);

    // fork: weight conversion on s2, overlapped with routing chain + GEMM1
    cudaEventRecord(ev_fork, 0);
    cudaStreamWaitEvent(s2, ev_fork, 0);
    convw_kernel<true ><<<2048, 256, 0, s2>>>(w1);
    cudaEventRecord(ev_w1, s2);
    convw_kernel<false><<<2048, 256, 0, s2>>>(w2);
    cudaEventRecord(ev_w2, s2);

    // main stream: routing chain
    zero_kernel<<<1, 32>>>();
    gate_kernel<<<N_TOK / 4, 128>>>(x, gate_w, gate_b);
    prefix_kernel<<<1, 32>>>();
    assign_kernel<<<N_TOK / 256, 256>>>();
    gather_kernel<<<dim3(32, NE), 256>>>(x);

    cudaStreamWaitEvent(0, ev_w1, 0);
    ffn_mma_kernel<DIM, FF, 256, true ><<<dim3(FF / 256, 32, NE), 256, SMEM_G1>>>(b1);
    cudaStreamWaitEvent(0, ev_w2, 0);
    ffn_mma_kernel<FF, DIM, 128, false><<<dim3(DIM / 128, 32, NE), 256, SMEM_G2>>>(b2);
    ln_kernel<<<N_TOK, 256>>>(ln_g, ln_b, out);
}

// round 12
// speedup vs baseline: 1.4476x; 1.4476x over previous
#include <cuda_runtime.h>
#include <cuda_fp16.h>
#include <cstdint>
#include <math.h>

// ---------------- problem constants ----------------
#define N_TOK 4096
#define DIM   1024
#define FF    4096
#define NE    8
#define TEMP  0.9f
#define EPS   1e-5f
#define PADMAX 9216

// ---------------- static device scratch ----------------
__device__ __half g_Xe[(size_t)PADMAX * DIM];    // fp16 gathered X
__device__ __half g_H [(size_t)PADMAX * FF];     // fp16 gelu acts
__device__ float  g_Y [(size_t)PADMAX * DIM];    // fp32 expert outputs
__device__ __half g_w1h[(size_t)NE * DIM * FF];  // fp16 w1
__device__ __half g_w2h[(size_t)NE * FF * DIM];  // fp16 w2
__device__ int   g_e0[N_TOK], g_e1[N_TOK];
__device__ float g_p0[N_TOK], g_p1[N_TOK];
__device__ int   g_pp0[N_TOK], g_pp1[N_TOK];
__device__ int   g_counts[NE], g_poff[NE], g_cursor[NE];
__device__ int   g_rowtok[PADMAX];

// ---------------- helpers ----------------
__device__ __forceinline__ uint32_t smem_u32(const void* p) {
    uint32_t a;
    asm("{ .reg .u64 t; cvta.to.shared.u64 t, %1; cvt.u32.u64 %0, t; }" : "=r"(a) : "l"(p));
    return a;
}
__device__ __forceinline__ void cp_async16(uint32_t dst, const void* src) {
    asm volatile("cp.async.cg.shared.global [%0], [%1], 16;" :: "r"(dst), "l"(src));
}
__device__ __forceinline__ uint32_t pack_f16x2(float lo, float hi) {
    uint32_t d;
    asm("cvt.rn.f16x2.f32 %0, %1, %2;" : "=r"(d) : "f"(hi), "f"(lo));
    return d;
}
__device__ __forceinline__ void ldmx4(uint32_t* r, uint32_t addr) {
    asm volatile("ldmatrix.sync.aligned.m8n8.x4.shared.b16 {%0,%1,%2,%3}, [%4];"
        : "=r"(r[0]), "=r"(r[1]), "=r"(r[2]), "=r"(r[3]) : "r"(addr));
}
__device__ __forceinline__ void ldmx4_t(uint32_t* r, uint32_t addr) {
    asm volatile("ldmatrix.sync.aligned.m8n8.x4.trans.shared.b16 {%0,%1,%2,%3}, [%4];"
        : "=r"(r[0]), "=r"(r[1]), "=r"(r[2]), "=r"(r[3]) : "r"(addr));
}
__device__ __forceinline__ void mma_f16(float* c, const uint32_t* a, const uint32_t* b) {
    asm volatile(
        "mma.sync.aligned.m16n8k16.row.col.f32.f16.f16.f32 "
        "{%0,%1,%2,%3}, {%4,%5,%6,%7}, {%8,%9}, {%0,%1,%2,%3};"
        : "+f"(c[0]), "+f"(c[1]), "+f"(c[2]), "+f"(c[3])
        : "r"(a[0]), "r"(a[1]), "r"(a[2]), "r"(a[3]), "r"(b[0]), "r"(b[1]));
}
__device__ __forceinline__ float warp_sum(float v) {
#pragma unroll
    for (int o = 16; o > 0; o >>= 1) v += __shfl_xor_sync(0xffffffffu, v, o);
    return v;
}

// ---------------- weight fp16 pre-conversion ----------------
__global__ __launch_bounds__(256)
void convw_kernel(const float* __restrict__ w1, const float* __restrict__ w2) {
    const size_t total4 = (size_t)NE * DIM * FF / 4;
    size_t i = (size_t)blockIdx.x * 256 + threadIdx.x;
    const float4* s1 = reinterpret_cast<const float4*>(w1);
    const float4* s2 = reinterpret_cast<const float4*>(w2);
    uint2* d1 = reinterpret_cast<uint2*>(g_w1h);
    uint2* d2 = reinterpret_cast<uint2*>(g_w2h);
    for (size_t j = i; j < total4; j += (size_t)gridDim.x * 256) {
        float4 v = s1[j];
        d1[j] = make_uint2(pack_f16x2(v.x, v.y), pack_f16x2(v.z, v.w));
        float4 u = s2[j];
        d2[j] = make_uint2(pack_f16x2(u.x, u.y), pack_f16x2(u.z, u.w));
    }
}

// ---------------- small kernels ----------------
__global__ void zero_kernel() {
    if (threadIdx.x < NE) g_counts[threadIdx.x] = 0;
}

// one warp per token, float4 loads of x
__global__ __launch_bounds__(256)
void gate_kernel(const float* __restrict__ x,
                 const float* __restrict__ gw,
                 const float* __restrict__ gb) {
    int warp = threadIdx.x >> 5, lane = threadIdx.x & 31;
    int t = blockIdx.x * 8 + warp;
    if (t >= N_TOK) return;
    float acc[NE];
#pragma unroll
    for (int e = 0; e < NE; e++) acc[e] = 0.f;
    const float4* xr = reinterpret_cast<const float4*>(x + (size_t)t * DIM);
#pragma unroll
    for (int it = 0; it < DIM / 128; it++) {
        int d4 = it * 32 + lane;             // float4 index; d = 4*d4
        float4 xv = xr[d4];
        const float4* g4 = reinterpret_cast<const float4*>(gw + (size_t)d4 * 4 * NE);
#pragma unroll
        for (int j = 0; j < 4; j++) {
            float xs = j == 0 ? xv.x : (j == 1 ? xv.y : (j == 2 ? xv.z : xv.w));
            float4 a = g4[2 * j], b = g4[2 * j + 1];
            acc[0] += xs * a.x; acc[1] += xs * a.y; acc[2] += xs * a.z; acc[3] += xs * a.w;
            acc[4] += xs * b.x; acc[5] += xs * b.y; acc[6] += xs * b.z; acc[7] += xs * b.w;
        }
    }
#pragma unroll
    for (int e = 0; e < NE; e++) acc[e] = warp_sum(acc[e]);
    if (lane == 0) {
        float lg[NE];
#pragma unroll
        for (int e = 0; e < NE; e++) lg[e] = (acc[e] + gb[e]) / TEMP;
        int i0 = 0;
#pragma unroll
        for (int e = 1; e < NE; e++) if (lg[e] > lg[i0]) i0 = e;
        int i1 = (i0 == 0) ? 1 : 0;
#pragma unroll
        for (int e = 0; e < NE; e++)
            if (e != i0 && lg[e] > lg[i1]) i1 = e;
        float ev = expf(lg[i1] - lg[i0]);
        float s = 1.f + ev;
        g_e0[t] = i0; g_e1[t] = i1;
        g_p0[t] = 1.f / s; g_p1[t] = ev / s;
        atomicAdd(&g_counts[i0], 1);
        atomicAdd(&g_counts[i1], 1);
    }
}

__global__ void prefix_kernel() {
    if (threadIdx.x == 0) {
        int s = 0;
        for (int e = 0; e < NE; e++) {
            g_poff[e] = s;
            s += ((g_counts[e] + 127) / 128) * 128;
            g_cursor[e] = 0;
        }
    }
}

__global__ void assign_kernel() {
    int t = blockIdx.x * 256 + threadIdx.x;
    if (t >= N_TOK) return;
    int e0 = g_e0[t], e1 = g_e1[t];
    int p = g_poff[e0] + atomicAdd(&g_cursor[e0], 1);
    g_rowtok[p] = t; g_pp0[t] = p;
    int q = g_poff[e1] + atomicAdd(&g_cursor[e1], 1);
    g_rowtok[q] = t; g_pp1[t] = q;
}

// gather + fp16-convert selected token rows into padded per-expert slabs
__global__ void gather_kernel(const float* __restrict__ x) {
    int e  = blockIdx.y;
    int mt = blockIdx.x;
    int cnt = g_counts[e];
    if (mt * 128 >= cnt) return;
    int base = g_poff[e] + mt * 128;
    int tid = threadIdx.x;
    const float4* x4 = reinterpret_cast<const float4*>(x);
    uint2* o2 = reinterpret_cast<uint2*>(g_Xe);
#pragma unroll 4
    for (int i = 0; i < 128; i++) {
        if (mt * 128 + i < cnt) {
            int tok = g_rowtok[base + i];
            float4 v = x4[(size_t)tok * (DIM / 4) + tid];
            o2[(size_t)(base + i) * (DIM / 4) + tid] =
                make_uint2(pack_f16x2(v.x, v.y), pack_f16x2(v.z, v.w));
        }
    }
}

// ---------------- fp16 mma.sync GEMM (all-fp16 operands, ldmatrix) ----------------
// CTA tile 128xBN, BK=32, 3-stage cp.async pipeline, one sync per K-chunk.
// 256 threads = 8 warps (2m x 4n), warp tile 64 x BN/4, mma m16n8k16.
#define STAGES 3
#define A_STRH 40
#define A_STGH (128 * A_STRH)              // halfs per stage
template<int BN> struct BC { static const int STRH = BN + 8; static const int STGH = 32 * (BN + 8); };
#define SMEM_G1 (STAGES * (A_STGH + BC<256>::STGH) * 2)
#define SMEM_G2 (STAGES * (A_STGH + BC<128>::STGH) * 2)

template<int K, int NF, int BN, bool GELU>
__global__ __launch_bounds__(256, (BN == 128 ? 2 : 1))
void ffn_mma_kernel(const float* __restrict__ bias_in) {
    constexpr int BSTRH = BN + 8;
    constexpr int BSTGH = 32 * BSTRH;
    constexpr int WN    = BN / 4;
    constexpr int NFR   = WN / 8;

    int e = blockIdx.z;
    int cnt = g_counts[e];
    int mt = blockIdx.y;
    if (mt * 128 >= cnt) return;
    int m0 = g_poff[e] + mt * 128;
    int n0 = blockIdx.x * BN;

    const __half* Abase = (GELU ? g_Xe : g_H) + (size_t)m0 * K;
    const __half* Bbase = (GELU ? g_w1h : g_w2h) + (size_t)e * K * NF + n0;
    const float*  bias  = bias_in + (size_t)e * NF + n0;

    extern __shared__ __half smh[];
    __half* Asm = smh;
    __half* Bsm = smh + STAGES * A_STGH;
    uint32_t sA32 = smem_u32(Asm), sB32 = smem_u32(Bsm);

    int tid = threadIdx.x, wid = tid >> 5, lane = tid & 31;
    int warp_m = wid & 1, warp_n = wid >> 1;
    int group = lane >> 2, tig = lane & 3;
    int rw = lane & 7, quad = lane >> 3;

    auto load_stage = [&](int kt, int s) {
        int k0 = kt * 32;
        uint32_t aD = sA32 + s * (A_STGH * 2);
        uint32_t bD = sB32 + s * (BSTGH * 2);
#pragma unroll
        for (int i = 0; i < 2; i++) {            // A: 128 rows x 4 x 16B
            int idx = tid + i * 256;
            int row = idx >> 2, c4 = idx & 3;
            cp_async16(aD + row * (A_STRH * 2) + c4 * 16,
                       Abase + (size_t)row * K + k0 + c4 * 8);
        }
#pragma unroll
        for (int i = 0; i < BN / 64; i++) {      // B: 32 rows x BN/8 x 16B
            int idx = tid + i * 256;
            int kk = idx / (BN / 8), c8 = idx % (BN / 8);
            cp_async16(bD + (kk * BSTRH + c8 * 8) * 2,
                       Bbase + (size_t)(k0 + kk) * NF + c8 * 8);
        }
        asm volatile("cp.async.commit_group;");
    };

    float acc[4][NFR][4];
#pragma unroll
    for (int i = 0; i < 4; i++)
#pragma unroll
        for (int j = 0; j < NFR; j++)
#pragma unroll
            for (int q = 0; q < 4; q++) acc[i][j][q] = 0.f;

    const int ktiles = K / 32;
    load_stage(0, 0);
    load_stage(1, 1);

    for (int kt = 0; kt < ktiles; kt++) {
        if (kt == ktiles - 1)
            asm volatile("cp.async.wait_group 0;" ::: "memory");
        else
            asm volatile("cp.async.wait_group 1;" ::: "memory");
        __syncthreads();

        if (kt + 2 < ktiles)
            load_stage(kt + 2, (kt + 2) % STAGES);

        int s = kt % STAGES;
        uint32_t aS = sA32 + s * (A_STGH * 2);
        uint32_t bS = sB32 + s * (BSTGH * 2);
#pragma unroll
        for (int ks = 0; ks < 2; ks++) {         // two k16 steps per K32 chunk
            int kb = ks * 16;
            uint32_t a[4][4], b[NFR][2];
#pragma unroll
            for (int m = 0; m < 4; m++) {
                int row = warp_m * 64 + m * 16 + rw + (quad & 1) * 8;
                int col = kb + (quad >> 1) * 8;
                ldmx4(a[m], aS + (row * A_STRH + col) * 2);
            }
#pragma unroll
            for (int n2 = 0; n2 < NFR / 2; n2++) {
                uint32_t r[4];
                int krow = kb + rw + (quad & 1) * 8;
                int col  = warp_n * WN + n2 * 16 + (quad >> 1) * 8;
                ldmx4_t(r, bS + (krow * BSTRH + col) * 2);
                b[2 * n2][0] = r[0]; b[2 * n2][1] = r[1];
                b[2 * n2 + 1][0] = r[2]; b[2 * n2 + 1][1] = r[3];
            }
#pragma unroll
            for (int m = 0; m < 4; m++)
#pragma unroll
                for (int n = 0; n < NFR; n++)
                    mma_f16(acc[m][n], a[m], b[n]);
        }
    }

    // epilogue: bias (+gelu); GEMM1 stores fp16 H, GEMM2 stores fp32 Y
#pragma unroll
    for (int m = 0; m < 4; m++) {
        int r0 = m0 + warp_m * 64 + m * 16 + group;
#pragma unroll
        for (int n = 0; n < NFR; n++) {
            int c = warp_n * WN + n * 8 + tig * 2;
            float bv0 = bias[c], bv1 = bias[c + 1];
#pragma unroll
            for (int h = 0; h < 2; h++) {
                float v0 = acc[m][n][h * 2 + 0] + bv0;
                float v1 = acc[m][n][h * 2 + 1] + bv1;
                if (GELU) {
                    v0 = 0.5f * v0 * (1.f + erff(v0 * 0.70710678118654752f));
                    v1 = 0.5f * v1 * (1.f + erff(v1 * 0.70710678118654752f));
                    *reinterpret_cast<uint32_t*>(
                        g_H + (size_t)(r0 + h * 8) * NF + n0 + c) = pack_f16x2(v0, v1);
                } else {
                    *reinterpret_cast<float2*>(
                        g_Y + (size_t)(r0 + h * 8) * NF + n0 + c) = make_float2(v0, v1);
                }
            }
        }
    }
}

// ---------------- combine + LayerNorm ----------------
__global__ void ln_kernel(const float* __restrict__ ln_g,
                          const float* __restrict__ ln_b,
                          float* __restrict__ out) {
    int t = blockIdx.x;
    __shared__ float sv[DIM];
    __shared__ float rs[8], rq[8];
    int tid = threadIdx.x;
    float p0 = g_p0[t], p1 = g_p1[t];
    const float* ya = g_Y + (size_t)g_pp0[t] * DIM;
    const float* yb = g_Y + (size_t)g_pp1[t] * DIM;
    float lsum = 0.f, lsq = 0.f;
    for (int d = tid; d < DIM; d += 256) {
        float v = p0 * ya[d] + p1 * yb[d];
        sv[d] = v;
        lsum += v; lsq += v * v;
    }
    lsum = warp_sum(lsum); lsq = warp_sum(lsq);
    int lane = tid & 31, wid = tid >> 5;
    if (lane == 0) { rs[wid] = lsum; rq[wid] = lsq; }
    __syncthreads();
    if (tid == 0) {
        float s = 0.f, q = 0.f;
#pragma unroll
        for (int w = 0; w < 8; w++) { s += rs[w]; q += rq[w]; }
        rs[0] = s; rq[0] = q;
    }
    __syncthreads();
    float mu  = rs[0] / DIM;
    float var = rq[0] / DIM - mu * mu;
    float inv = rsqrtf(var + EPS);
    float* outr = out + (size_t)t * DIM;
    for (int d = tid; d < DIM; d += 256)
        outr[d] = (sv[d] - mu) * inv * ln_g[d] + ln_b[d];
}

// ---------------- launch ----------------
extern "C" void kernel_launch(void* const* d_in, const int* in_sizes, int n_in,
                              void* d_out, int out_size) {
    const float* x      = (const float*)d_in[0];
    const float* gate_w = (const float*)d_in[1];
    const float* gate_b = (const float*)d_in[2];
    const float* w1     = (const float*)d_in[3];
    const float* b1     = (const float*)d_in[4];
    const float* w2     = (const float*)d_in[5];
    const float* b2     = (const float*)d_in[6];
    const float* ln_g   = (const float*)d_in[7];
    const float* ln_b   = (const float*)d_in[8];
    float* out = (float*)d_out;

    cudaFuncSetAttribute(ffn_mma_kernel<DIM, FF, 256, true>,
                         cudaFuncAttributeMaxDynamicSharedMemorySize, SMEM_G1);
    cudaFuncSetAttribute(ffn_mma_kernel<FF, DIM, 128, false>,
                         cudaFuncAttributeMaxDynamicSharedMemorySize, SMEM_G2);

    zero_kernel<<<1, 32>>>();
    convw_kernel<<<4096, 256>>>(w1, w2);
    gate_kernel<<<N_TOK / 8, 256>>>(x, gate_w, gate_b);
    prefix_kernel<<<1, 32>>>();
    assign_kernel<<<N_TOK / 256, 256>>>();
    gather_kernel<<<dim3(32, NE), 256>>>(x);
    ffn_mma_kernel<DIM, FF, 256, true ><<<dim3(FF / 256, 32, NE), 256, SMEM_G1>>>(b1);
    ffn_mma_kernel<FF, DIM, 128, false><<<dim3(DIM / 128, 32, NE), 256, SMEM_G2>>>(b2);
    ln_kernel<<<N_TOK, 256>>>(ln_g, ln_b, out);
}

// round 13
// speedup vs baseline: 1.5691x; 1.0839x over previous
#include <cuda_runtime.h>
#include <cuda_fp16.h>
#include <cstdint>
#include <math.h>

// ---------------- problem constants ----------------
#define N_TOK 4096
#define DIM   1024
#define FF    4096
#define NE    8
#define TEMP  0.9f
#define EPS   1e-5f
#define PADMAX 9216
#define GATE_BLOCKS 512
#define CONV_BLOCKS 4096

// ---------------- static device scratch ----------------
__device__ __half g_Xe[(size_t)PADMAX * DIM];    // fp16 gathered X
__device__ __half g_H [(size_t)PADMAX * FF];     // fp16 gelu acts
__device__ float  g_Y [(size_t)PADMAX * DIM];    // fp32 expert outputs
__device__ __half g_w1h[(size_t)NE * DIM * FF];  // fp16 w1
__device__ __half g_w2h[(size_t)NE * FF * DIM];  // fp16 w2
__device__ int   g_e0[N_TOK], g_e1[N_TOK];
__device__ float g_p0[N_TOK], g_p1[N_TOK];
__device__ int   g_pp0[N_TOK], g_pp1[N_TOK];
__device__ int   g_counts[NE], g_poff[NE], g_cursor[NE];

// ---------------- helpers ----------------
__device__ __forceinline__ uint32_t smem_u32(const void* p) {
    uint32_t a;
    asm("{ .reg .u64 t; cvta.to.shared.u64 t, %1; cvt.u32.u64 %0, t; }" : "=r"(a) : "l"(p));
    return a;
}
__device__ __forceinline__ void cp_async16(uint32_t dst, const void* src) {
    asm volatile("cp.async.cg.shared.global [%0], [%1], 16;" :: "r"(dst), "l"(src));
}
__device__ __forceinline__ uint32_t pack_f16x2(float lo, float hi) {
    uint32_t d;
    asm("cvt.rn.f16x2.f32 %0, %1, %2;" : "=r"(d) : "f"(hi), "f"(lo));
    return d;
}
__device__ __forceinline__ void ldmx4(uint32_t* r, uint32_t addr) {
    asm volatile("ldmatrix.sync.aligned.m8n8.x4.shared.b16 {%0,%1,%2,%3}, [%4];"
        : "=r"(r[0]), "=r"(r[1]), "=r"(r[2]), "=r"(r[3]) : "r"(addr));
}
__device__ __forceinline__ void ldmx4_t(uint32_t* r, uint32_t addr) {
    asm volatile("ldmatrix.sync.aligned.m8n8.x4.trans.shared.b16 {%0,%1,%2,%3}, [%4];"
        : "=r"(r[0]), "=r"(r[1]), "=r"(r[2]), "=r"(r[3]) : "r"(addr));
}
__device__ __forceinline__ void mma_f16(float* c, const uint32_t* a, const uint32_t* b) {
    asm volatile(
        "mma.sync.aligned.m16n8k16.row.col.f32.f16.f16.f32 "
        "{%0,%1,%2,%3}, {%4,%5,%6,%7}, {%8,%9}, {%0,%1,%2,%3};"
        : "+f"(c[0]), "+f"(c[1]), "+f"(c[2]), "+f"(c[3])
        : "r"(a[0]), "r"(a[1]), "r"(a[2]), "r"(a[3]), "r"(b[0]), "r"(b[1]));
}
__device__ __forceinline__ float warp_sum(float v) {
#pragma unroll
    for (int o = 16; o > 0; o >>= 1) v += __shfl_xor_sync(0xffffffffu, v, o);
    return v;
}

// ---------------- fused gate + weight fp16 conversion ----------------
// blocks [0, GATE_BLOCKS): gate (8 warps = 8 tokens per block), no count atomics
// blocks [GATE_BLOCKS, GATE_BLOCKS+CONV_BLOCKS): grid-stride fp16 conversion of w1+w2
__global__ __launch_bounds__(256)
void fused_gate_convw(const float* __restrict__ x,
                      const float* __restrict__ gw,
                      const float* __restrict__ gb,
                      const float* __restrict__ w1,
                      const float* __restrict__ w2) {
    if (blockIdx.x < GATE_BLOCKS) {
        int warp = threadIdx.x >> 5, lane = threadIdx.x & 31;
        int t = blockIdx.x * 8 + warp;
        float acc[NE];
#pragma unroll
        for (int e = 0; e < NE; e++) acc[e] = 0.f;
        const float* xr = x + (size_t)t * DIM;
        for (int d = lane; d < DIM; d += 32) {
            float xv = xr[d];
            const float4* g4 = reinterpret_cast<const float4*>(gw + (size_t)d * NE);
            float4 a = g4[0], b = g4[1];
            acc[0] += xv * a.x; acc[1] += xv * a.y; acc[2] += xv * a.z; acc[3] += xv * a.w;
            acc[4] += xv * b.x; acc[5] += xv * b.y; acc[6] += xv * b.z; acc[7] += xv * b.w;
        }
#pragma unroll
        for (int e = 0; e < NE; e++) acc[e] = warp_sum(acc[e]);
        if (lane == 0) {
            float lg[NE];
#pragma unroll
            for (int e = 0; e < NE; e++) lg[e] = (acc[e] + gb[e]) / TEMP;
            int i0 = 0;
#pragma unroll
            for (int e = 1; e < NE; e++) if (lg[e] > lg[i0]) i0 = e;
            int i1 = (i0 == 0) ? 1 : 0;
#pragma unroll
            for (int e = 0; e < NE; e++)
                if (e != i0 && lg[e] > lg[i1]) i1 = e;
            float ev = expf(lg[i1] - lg[i0]);
            float s = 1.f + ev;
            g_e0[t] = i0; g_e1[t] = i1;
            g_p0[t] = 1.f / s; g_p1[t] = ev / s;
        }
    } else {
        const size_t total4 = (size_t)NE * DIM * FF / 4;
        size_t i = (size_t)(blockIdx.x - GATE_BLOCKS) * 256 + threadIdx.x;
        const float4* s1 = reinterpret_cast<const float4*>(w1);
        const float4* s2 = reinterpret_cast<const float4*>(w2);
        uint2* d1 = reinterpret_cast<uint2*>(g_w1h);
        uint2* d2 = reinterpret_cast<uint2*>(g_w2h);
        for (size_t j = i; j < total4; j += (size_t)CONV_BLOCKS * 256) {
            float4 v = s1[j];
            d1[j] = make_uint2(pack_f16x2(v.x, v.y), pack_f16x2(v.z, v.w));
            float4 u = s2[j];
            d2[j] = make_uint2(pack_f16x2(u.x, u.y), pack_f16x2(u.z, u.w));
        }
    }
}

// ---------------- prefix: histogram + offsets (replaces zero+count-atomics) ----------------
__global__ void prefix_kernel() {
    __shared__ int h[NE];
    int tid = threadIdx.x;
    if (tid < NE) h[tid] = 0;
    __syncthreads();
    for (int t = tid; t < N_TOK; t += 256) {
        atomicAdd(&h[g_e0[t]], 1);
        atomicAdd(&h[g_e1[t]], 1);
    }
    __syncthreads();
    if (tid == 0) {
        int s = 0;
#pragma unroll
        for (int e = 0; e < NE; e++) {
            g_counts[e] = h[e];
            g_poff[e] = s;
            s += ((h[e] + 127) / 128) * 128;
            g_cursor[e] = 0;
        }
    }
}

// ---------------- scatter: fused assign + gather (token-parallel, warp/token) ----------------
__global__ __launch_bounds__(256)
void scatter_kernel(const float* __restrict__ x) {
    int warp = threadIdx.x >> 5, lane = threadIdx.x & 31;
    int t = blockIdx.x * 8 + warp;
    int e0 = g_e0[t], e1 = g_e1[t];
    int p = 0, q = 0;
    if (lane == 0) {
        p = g_poff[e0] + atomicAdd(&g_cursor[e0], 1);
        q = g_poff[e1] + atomicAdd(&g_cursor[e1], 1);
        g_pp0[t] = p; g_pp1[t] = q;
    }
    p = __shfl_sync(0xffffffffu, p, 0);
    q = __shfl_sync(0xffffffffu, q, 0);
    const float4* xr = reinterpret_cast<const float4*>(x + (size_t)t * DIM);
    uint2* oa = reinterpret_cast<uint2*>(g_Xe) + (size_t)p * (DIM / 4);
    uint2* ob = reinterpret_cast<uint2*>(g_Xe) + (size_t)q * (DIM / 4);
#pragma unroll
    for (int i = 0; i < DIM / 128; i++) {
        int idx = lane + 32 * i;
        float4 v = xr[idx];
        uint2 h = make_uint2(pack_f16x2(v.x, v.y), pack_f16x2(v.z, v.w));
        oa[idx] = h;
        ob[idx] = h;
    }
}

// ---------------- fp16 mma.sync GEMM (all-fp16 operands, ldmatrix) ----------------
// CTA tile 128xBN, BK=32, 3-stage cp.async pipeline, one sync per K-chunk.
// 256 threads = 8 warps (2m x 4n), warp tile 64 x BN/4, mma m16n8k16.
#define STAGES 3
#define A_STRH 40
#define A_STGH (128 * A_STRH)              // halfs per stage
template<int BN> struct BC { static const int STRH = BN + 8; static const int STGH = 32 * (BN + 8); };
#define SMEM_G1 (STAGES * (A_STGH + BC<256>::STGH) * 2)
#define SMEM_G2 (STAGES * (A_STGH + BC<128>::STGH) * 2)

template<int K, int NF, int BN, bool GELU>
__global__ __launch_bounds__(256, (BN == 128 ? 2 : 1))
void ffn_mma_kernel(const float* __restrict__ bias_in) {
    constexpr int BSTRH = BN + 8;
    constexpr int BSTGH = 32 * BSTRH;
    constexpr int WN    = BN / 4;
    constexpr int NFR   = WN / 8;

    int e = blockIdx.z;
    int cnt = g_counts[e];
    int mt = blockIdx.y;
    if (mt * 128 >= cnt) return;
    int m0 = g_poff[e] + mt * 128;
    int n0 = blockIdx.x * BN;

    const __half* Abase = (GELU ? g_Xe : g_H) + (size_t)m0 * K;
    const __half* Bbase = (GELU ? g_w1h : g_w2h) + (size_t)e * K * NF + n0;
    const float*  bias  = bias_in + (size_t)e * NF + n0;

    extern __shared__ __half smh[];
    __half* Asm = smh;
    __half* Bsm = smh + STAGES * A_STGH;
    uint32_t sA32 = smem_u32(Asm), sB32 = smem_u32(Bsm);

    int tid = threadIdx.x, wid = tid >> 5, lane = tid & 31;
    int warp_m = wid & 1, warp_n = wid >> 1;
    int group = lane >> 2, tig = lane & 3;
    int rw = lane & 7, quad = lane >> 3;

    auto load_stage = [&](int kt, int s) {
        int k0 = kt * 32;
        uint32_t aD = sA32 + s * (A_STGH * 2);
        uint32_t bD = sB32 + s * (BSTGH * 2);
#pragma unroll
        for (int i = 0; i < 2; i++) {            // A: 128 rows x 4 x 16B
            int idx = tid + i * 256;
            int row = idx >> 2, c4 = idx & 3;
            cp_async16(aD + row * (A_STRH * 2) + c4 * 16,
                       Abase + (size_t)row * K + k0 + c4 * 8);
        }
#pragma unroll
        for (int i = 0; i < BN / 64; i++) {      // B: 32 rows x BN/8 x 16B
            int idx = tid + i * 256;
            int kk = idx / (BN / 8), c8 = idx % (BN / 8);
            cp_async16(bD + (kk * BSTRH + c8 * 8) * 2,
                       Bbase + (size_t)(k0 + kk) * NF + c8 * 8);
        }
        asm volatile("cp.async.commit_group;");
    };

    float acc[4][NFR][4];
#pragma unroll
    for (int i = 0; i < 4; i++)
#pragma unroll
        for (int j = 0; j < NFR; j++)
#pragma unroll
            for (int q = 0; q < 4; q++) acc[i][j][q] = 0.f;

    const int ktiles = K / 32;
    load_stage(0, 0);
    load_stage(1, 1);

    for (int kt = 0; kt < ktiles; kt++) {
        if (kt == ktiles - 1)
            asm volatile("cp.async.wait_group 0;" ::: "memory");
        else
            asm volatile("cp.async.wait_group 1;" ::: "memory");
        __syncthreads();

        if (kt + 2 < ktiles)
            load_stage(kt + 2, (kt + 2) % STAGES);

        int s = kt % STAGES;
        uint32_t aS = sA32 + s * (A_STGH * 2);
        uint32_t bS = sB32 + s * (BSTGH * 2);
#pragma unroll
        for (int ks = 0; ks < 2; ks++) {         // two k16 steps per K32 chunk
            int kb = ks * 16;
            uint32_t a[4][4], b[NFR][2];
#pragma unroll
            for (int m = 0; m < 4; m++) {
                int row = warp_m * 64 + m * 16 + rw + (quad & 1) * 8;
                int col = kb + (quad >> 1) * 8;
                ldmx4(a[m], aS + (row * A_STRH + col) * 2);
            }
#pragma unroll
            for (int n2 = 0; n2 < NFR / 2; n2++) {
                uint32_t r[4];
                int krow = kb + rw + (quad & 1) * 8;
                int col  = warp_n * WN + n2 * 16 + (quad >> 1) * 8;
                ldmx4_t(r, bS + (krow * BSTRH + col) * 2);
                b[2 * n2][0] = r[0]; b[2 * n2][1] = r[1];
                b[2 * n2 + 1][0] = r[2]; b[2 * n2 + 1][1] = r[3];
            }
#pragma unroll
            for (int m = 0; m < 4; m++)
#pragma unroll
                for (int n = 0; n < NFR; n++)
                    mma_f16(acc[m][n], a[m], b[n]);
        }
    }

    // epilogue: bias (+gelu); GEMM1 stores fp16 H, GEMM2 stores fp32 Y
#pragma unroll
    for (int m = 0; m < 4; m++) {
        int r0 = m0 + warp_m * 64 + m * 16 + group;
#pragma unroll
        for (int n = 0; n < NFR; n++) {
            int c = warp_n * WN + n * 8 + tig * 2;
            float bv0 = bias[c], bv1 = bias[c + 1];
#pragma unroll
            for (int h = 0; h < 2; h++) {
                float v0 = acc[m][n][h * 2 + 0] + bv0;
                float v1 = acc[m][n][h * 2 + 1] + bv1;
                if (GELU) {
                    v0 = 0.5f * v0 * (1.f + erff(v0 * 0.70710678118654752f));
                    v1 = 0.5f * v1 * (1.f + erff(v1 * 0.70710678118654752f));
                    *reinterpret_cast<uint32_t*>(
                        g_H + (size_t)(r0 + h * 8) * NF + n0 + c) = pack_f16x2(v0, v1);
                } else {
                    *reinterpret_cast<float2*>(
                        g_Y + (size_t)(r0 + h * 8) * NF + n0 + c) = make_float2(v0, v1);
                }
            }
        }
    }
}

// ---------------- combine + LayerNorm ----------------
__global__ void ln_kernel(const float* __restrict__ ln_g,
                          const float* __restrict__ ln_b,
                          float* __restrict__ out) {
    int t = blockIdx.x;
    __shared__ float sv[DIM];
    __shared__ float rs[8], rq[8];
    int tid = threadIdx.x;
    float p0 = g_p0[t], p1 = g_p1[t];
    const float* ya = g_Y + (size_t)g_pp0[t] * DIM;
    const float* yb = g_Y + (size_t)g_pp1[t] * DIM;
    float lsum = 0.f, lsq = 0.f;
    for (int d = tid; d < DIM; d += 256) {
        float v = p0 * ya[d] + p1 * yb[d];
        sv[d] = v;
        lsum += v; lsq += v * v;
    }
    lsum = warp_sum(lsum); lsq = warp_sum(lsq);
    int lane = tid & 31, wid = tid >> 5;
    if (lane == 0) { rs[wid] = lsum; rq[wid] = lsq; }
    __syncthreads();
    if (tid == 0) {
        float s = 0.f, q = 0.f;
#pragma unroll
        for (int w = 0; w < 8; w++) { s += rs[w]; q += rq[w]; }
        rs[0] = s; rq[0] = q;
    }
    __syncthreads();
    float mu  = rs[0] / DIM;
    float var = rq[0] / DIM - mu * mu;
    float inv = rsqrtf(var + EPS);
    float* outr = out + (size_t)t * DIM;
    for (int d = tid; d < DIM; d += 256)
        outr[d] = (sv[d] - mu) * inv * ln_g[d] + ln_b[d];
}

// ---------------- launch ----------------
extern "C" void kernel_launch(void* const* d_in, const int* in_sizes, int n_in,
                              void* d_out, int out_size) {
    const float* x      = (const float*)d_in[0];
    const float* gate_w = (const float*)d_in[1];
    const float* gate_b = (const float*)d_in[2];
    const float* w1     = (const float*)d_in[3];
    const float* b1     = (const float*)d_in[4];
    const float* w2     = (const float*)d_in[5];
    const float* b2     = (const float*)d_in[6];
    const float* ln_g   = (const float*)d_in[7];
    const float* ln_b   = (const float*)d_in[8];
    float* out = (float*)d_out;

    cudaFuncSetAttribute(ffn_mma_kernel<DIM, FF, 256, true>,
                         cudaFuncAttributeMaxDynamicSharedMemorySize, SMEM_G1);
    cudaFuncSetAttribute(ffn_mma_kernel<FF, DIM, 128, false>,
                         cudaFuncAttributeMaxDynamicSharedMemorySize, SMEM_G2);

    fused_gate_convw<<<GATE_BLOCKS + CONV_BLOCKS, 256>>>(x, gate_w, gate_b, w1, w2);
    prefix_kernel<<<1, 256>>>();
    scatter_kernel<<<N_TOK / 8, 256>>>(x);
    ffn_mma_kernel<DIM, FF, 256, true ><<<dim3(FF / 256, 32, NE), 256, SMEM_G1>>>(b1);
    ffn_mma_kernel<FF, DIM, 128, false><<<dim3(DIM / 128, 32, NE), 256, SMEM_G2>>>(b2);
    ln_kernel<<<N_TOK, 256>>>(ln_g, ln_b, out);
}

// round 14
// speedup vs baseline: 1.6934x; 1.0793x over previous
#include <cuda_runtime.h>
#include <cuda_fp16.h>
#include <cstdint>
#include <math.h>

// ---------------- problem constants ----------------
#define N_TOK 4096
#define DIM   1024
#define FF    4096
#define NE    8
#define TEMP  0.9f
#define EPS   1e-5f
#define PADMAX 9216
#define GATE_BLOCKS 512
#define CONV_BLOCKS 4096

// ---------------- static device scratch ----------------
__device__ __half g_Xe[(size_t)PADMAX * DIM];    // fp16 gathered X
__device__ __half g_H [(size_t)PADMAX * FF];     // fp16 gelu acts
__device__ float  g_Y [(size_t)PADMAX * DIM];    // fp32 expert outputs
__device__ __half g_w1h[(size_t)NE * DIM * FF];  // fp16 w1
__device__ __half g_w2h[(size_t)NE * FF * DIM];  // fp16 w2
__device__ int   g_e0[N_TOK], g_e1[N_TOK];
__device__ float g_p0[N_TOK], g_p1[N_TOK];
__device__ int   g_pp0[N_TOK], g_pp1[N_TOK];
__device__ int   g_counts[NE], g_poff[NE], g_cursor[NE];

// ---------------- helpers ----------------
__device__ __forceinline__ uint32_t smem_u32(const void* p) {
    uint32_t a;
    asm("{ .reg .u64 t; cvta.to.shared.u64 t, %1; cvt.u32.u64 %0, t; }" : "=r"(a) : "l"(p));
    return a;
}
__device__ __forceinline__ void cp_async16(uint32_t dst, const void* src) {
    asm volatile("cp.async.cg.shared.global [%0], [%1], 16;" :: "r"(dst), "l"(src));
}
__device__ __forceinline__ uint32_t pack_f16x2(float lo, float hi) {
    uint32_t d;
    asm("cvt.rn.f16x2.f32 %0, %1, %2;" : "=r"(d) : "f"(hi), "f"(lo));
    return d;
}
__device__ __forceinline__ void ldmx4(uint32_t* r, uint32_t addr) {
    asm volatile("ldmatrix.sync.aligned.m8n8.x4.shared.b16 {%0,%1,%2,%3}, [%4];"
        : "=r"(r[0]), "=r"(r[1]), "=r"(r[2]), "=r"(r[3]) : "r"(addr));
}
__device__ __forceinline__ void ldmx4_t(uint32_t* r, uint32_t addr) {
    asm volatile("ldmatrix.sync.aligned.m8n8.x4.trans.shared.b16 {%0,%1,%2,%3}, [%4];"
        : "=r"(r[0]), "=r"(r[1]), "=r"(r[2]), "=r"(r[3]) : "r"(addr));
}
__device__ __forceinline__ void mma_f16(float* c, const uint32_t* a, const uint32_t* b) {
    asm volatile(
        "mma.sync.aligned.m16n8k16.row.col.f32.f16.f16.f32 "
        "{%0,%1,%2,%3}, {%4,%5,%6,%7}, {%8,%9}, {%0,%1,%2,%3};"
        : "+f"(c[0]), "+f"(c[1]), "+f"(c[2]), "+f"(c[3])
        : "r"(a[0]), "r"(a[1]), "r"(a[2]), "r"(a[3]), "r"(b[0]), "r"(b[1]));
}
__device__ __forceinline__ float warp_sum(float v) {
#pragma unroll
    for (int o = 16; o > 0; o >>= 1) v += __shfl_xor_sync(0xffffffffu, v, o);
    return v;
}

// ---------------- fused gate + weight fp16 conversion ----------------
__global__ __launch_bounds__(256)
void fused_gate_convw(const float* __restrict__ x,
                      const float* __restrict__ gw,
                      const float* __restrict__ gb,
                      const float* __restrict__ w1,
                      const float* __restrict__ w2) {
    if (blockIdx.x < GATE_BLOCKS) {
        int warp = threadIdx.x >> 5, lane = threadIdx.x & 31;
        int t = blockIdx.x * 8 + warp;
        float acc[NE];
#pragma unroll
        for (int e = 0; e < NE; e++) acc[e] = 0.f;
        const float* xr = x + (size_t)t * DIM;
        for (int d = lane; d < DIM; d += 32) {
            float xv = xr[d];
            const float4* g4 = reinterpret_cast<const float4*>(gw + (size_t)d * NE);
            float4 a = g4[0], b = g4[1];
            acc[0] += xv * a.x; acc[1] += xv * a.y; acc[2] += xv * a.z; acc[3] += xv * a.w;
            acc[4] += xv * b.x; acc[5] += xv * b.y; acc[6] += xv * b.z; acc[7] += xv * b.w;
        }
#pragma unroll
        for (int e = 0; e < NE; e++) acc[e] = warp_sum(acc[e]);
        if (lane == 0) {
            float lg[NE];
#pragma unroll
            for (int e = 0; e < NE; e++) lg[e] = (acc[e] + gb[e]) / TEMP;
            int i0 = 0;
#pragma unroll
            for (int e = 1; e < NE; e++) if (lg[e] > lg[i0]) i0 = e;
            int i1 = (i0 == 0) ? 1 : 0;
#pragma unroll
            for (int e = 0; e < NE; e++)
                if (e != i0 && lg[e] > lg[i1]) i1 = e;
            float ev = expf(lg[i1] - lg[i0]);
            float s = 1.f + ev;
            g_e0[t] = i0; g_e1[t] = i1;
            g_p0[t] = 1.f / s; g_p1[t] = ev / s;
        }
    } else {
        const size_t total4 = (size_t)NE * DIM * FF / 4;
        size_t i = (size_t)(blockIdx.x - GATE_BLOCKS) * 256 + threadIdx.x;
        const float4* s1 = reinterpret_cast<const float4*>(w1);
        const float4* s2 = reinterpret_cast<const float4*>(w2);
        uint2* d1 = reinterpret_cast<uint2*>(g_w1h);
        uint2* d2 = reinterpret_cast<uint2*>(g_w2h);
        for (size_t j = i; j < total4; j += (size_t)CONV_BLOCKS * 256) {
            float4 v = s1[j];
            d1[j] = make_uint2(pack_f16x2(v.x, v.y), pack_f16x2(v.z, v.w));
            float4 u = s2[j];
            d2[j] = make_uint2(pack_f16x2(u.x, u.y), pack_f16x2(u.z, u.w));
        }
    }
}

// ---------------- prefix: histogram + offsets ----------------
__global__ void prefix_kernel() {
    __shared__ int h[NE];
    int tid = threadIdx.x;
    if (tid < NE) h[tid] = 0;
    __syncthreads();
    for (int t = tid; t < N_TOK; t += 256) {
        atomicAdd(&h[g_e0[t]], 1);
        atomicAdd(&h[g_e1[t]], 1);
    }
    __syncthreads();
    if (tid == 0) {
        int s = 0;
#pragma unroll
        for (int e = 0; e < NE; e++) {
            g_counts[e] = h[e];
            g_poff[e] = s;
            s += ((h[e] + 127) / 128) * 128;
            g_cursor[e] = 0;
        }
    }
}

// ---------------- scatter: fused assign + gather ----------------
__global__ __launch_bounds__(256)
void scatter_kernel(const float* __restrict__ x) {
    int warp = threadIdx.x >> 5, lane = threadIdx.x & 31;
    int t = blockIdx.x * 8 + warp;
    int e0 = g_e0[t], e1 = g_e1[t];
    int p = 0, q = 0;
    if (lane == 0) {
        p = g_poff[e0] + atomicAdd(&g_cursor[e0], 1);
        q = g_poff[e1] + atomicAdd(&g_cursor[e1], 1);
        g_pp0[t] = p; g_pp1[t] = q;
    }
    p = __shfl_sync(0xffffffffu, p, 0);
    q = __shfl_sync(0xffffffffu, q, 0);
    const float4* xr = reinterpret_cast<const float4*>(x + (size_t)t * DIM);
    uint2* oa = reinterpret_cast<uint2*>(g_Xe) + (size_t)p * (DIM / 4);
    uint2* ob = reinterpret_cast<uint2*>(g_Xe) + (size_t)q * (DIM / 4);
#pragma unroll
    for (int i = 0; i < DIM / 128; i++) {
        int idx = lane + 32 * i;
        float4 v = xr[idx];
        uint2 h = make_uint2(pack_f16x2(v.x, v.y), pack_f16x2(v.z, v.w));
        oa[idx] = h;
        ob[idx] = h;
    }
}

// ---------------- fp16 mma.sync GEMM (all-fp16 operands, ldmatrix) ----------------
// CTA tile 128x128, BK=32, 3-stage cp.async pipeline, occupancy 2.
// 256 threads = 8 warps (2m x 4n), warp tile 64 x 32, mma m16n8k16.
#define STAGES 3
#define A_STRH 40
#define A_STGH (128 * A_STRH)              // halfs per stage
#define BSTRH_C (128 + 8)
#define BSTGH_C (32 * BSTRH_C)
#define SMEM_FFN (STAGES * (A_STGH + BSTGH_C) * 2)

template<int K, int NF, bool GELU>
__global__ __launch_bounds__(256, 2)
void ffn_mma_kernel(const float* __restrict__ bias_in) {
    constexpr int BN    = 128;
    constexpr int BSTRH = BN + 8;
    constexpr int BSTGH = 32 * BSTRH;
    constexpr int WN    = BN / 4;          // 32
    constexpr int NFR   = WN / 8;          // 4

    int e = blockIdx.z;
    int cnt = g_counts[e];
    int mt = blockIdx.y;
    if (mt * 128 >= cnt) return;
    int m0 = g_poff[e] + mt * 128;
    int n0 = blockIdx.x * BN;

    const __half* Abase = (GELU ? g_Xe : g_H) + (size_t)m0 * K;
    const __half* Bbase = (GELU ? g_w1h : g_w2h) + (size_t)e * K * NF + n0;
    const float*  bias  = bias_in + (size_t)e * NF + n0;

    extern __shared__ __half smh[];
    __half* Asm = smh;
    __half* Bsm = smh + STAGES * A_STGH;
    uint32_t sA32 = smem_u32(Asm), sB32 = smem_u32(Bsm);

    int tid = threadIdx.x, wid = tid >> 5, lane = tid & 31;
    int warp_m = wid & 1, warp_n = wid >> 1;
    int group = lane >> 2, tig = lane & 3;
    int rw = lane & 7, quad = lane >> 3;

    auto load_stage = [&](int kt, int s) {
        int k0 = kt * 32;
        uint32_t aD = sA32 + s * (A_STGH * 2);
        uint32_t bD = sB32 + s * (BSTGH * 2);
#pragma unroll
        for (int i = 0; i < 2; i++) {            // A: 128 rows x 4 x 16B
            int idx = tid + i * 256;
            int row = idx >> 2, c4 = idx & 3;
            cp_async16(aD + row * (A_STRH * 2) + c4 * 16,
                       Abase + (size_t)row * K + k0 + c4 * 8);
        }
#pragma unroll
        for (int i = 0; i < 2; i++) {            // B: 32 rows x 16 x 16B
            int idx = tid + i * 256;
            int kk = idx >> 4, c8 = idx & 15;
            cp_async16(bD + (kk * BSTRH + c8 * 8) * 2,
                       Bbase + (size_t)(k0 + kk) * NF + c8 * 8);
        }
        asm volatile("cp.async.commit_group;");
    };

    float acc[4][NFR][4];
#pragma unroll
    for (int i = 0; i < 4; i++)
#pragma unroll
        for (int j = 0; j < NFR; j++)
#pragma unroll
            for (int q = 0; q < 4; q++) acc[i][j][q] = 0.f;

    const int ktiles = K / 32;
    load_stage(0, 0);
    load_stage(1, 1);

    for (int kt = 0; kt < ktiles; kt++) {
        if (kt == ktiles - 1)
            asm volatile("cp.async.wait_group 0;" ::: "memory");
        else
            asm volatile("cp.async.wait_group 1;" ::: "memory");
        __syncthreads();

        if (kt + 2 < ktiles)
            load_stage(kt + 2, (kt + 2) % STAGES);

        int s = kt % STAGES;
        uint32_t aS = sA32 + s * (A_STGH * 2);
        uint32_t bS = sB32 + s * (BSTGH * 2);
#pragma unroll
        for (int ks = 0; ks < 2; ks++) {         // two k16 steps per K32 chunk
            int kb = ks * 16;
            uint32_t a[4][4], b[NFR][2];
#pragma unroll
            for (int m = 0; m < 4; m++) {
                int row = warp_m * 64 + m * 16 + rw + (quad & 1) * 8;
                int col = kb + (quad >> 1) * 8;
                ldmx4(a[m], aS + (row * A_STRH + col) * 2);
            }
#pragma unroll
            for (int n2 = 0; n2 < NFR / 2; n2++) {
                uint32_t r[4];
                int krow = kb + rw + (quad & 1) * 8;
                int col  = warp_n * WN + n2 * 16 + (quad >> 1) * 8;
                ldmx4_t(r, bS + (krow * BSTRH + col) * 2);
                b[2 * n2][0] = r[0]; b[2 * n2][1] = r[1];
                b[2 * n2 + 1][0] = r[2]; b[2 * n2 + 1][1] = r[3];
            }
#pragma unroll
            for (int m = 0; m < 4; m++)
#pragma unroll
                for (int n = 0; n < NFR; n++)
                    mma_f16(acc[m][n], a[m], b[n]);
        }
    }

    // epilogue: bias (+gelu); GEMM1 stores fp16 H, GEMM2 stores fp32 Y
#pragma unroll
    for (int m = 0; m < 4; m++) {
        int r0 = m0 + warp_m * 64 + m * 16 + group;
#pragma unroll
        for (int n = 0; n < NFR; n++) {
            int c = warp_n * WN + n * 8 + tig * 2;
            float bv0 = bias[c], bv1 = bias[c + 1];
#pragma unroll
            for (int h = 0; h < 2; h++) {
                float v0 = acc[m][n][h * 2 + 0] + bv0;
                float v1 = acc[m][n][h * 2 + 1] + bv1;
                if (GELU) {
                    v0 = 0.5f * v0 * (1.f + erff(v0 * 0.70710678118654752f));
                    v1 = 0.5f * v1 * (1.f + erff(v1 * 0.70710678118654752f));
                    *reinterpret_cast<uint32_t*>(
                        g_H + (size_t)(r0 + h * 8) * NF + n0 + c) = pack_f16x2(v0, v1);
                } else {
                    *reinterpret_cast<float2*>(
                        g_Y + (size_t)(r0 + h * 8) * NF + n0 + c) = make_float2(v0, v1);
                }
            }
        }
    }
}

// ---------------- combine + LayerNorm ----------------
__global__ void ln_kernel(const float* __restrict__ ln_g,
                          const float* __restrict__ ln_b,
                          float* __restrict__ out) {
    int t = blockIdx.x;
    __shared__ float sv[DIM];
    __shared__ float rs[8], rq[8];
    int tid = threadIdx.x;
    float p0 = g_p0[t], p1 = g_p1[t];
    const float* ya = g_Y + (size_t)g_pp0[t] * DIM;
    const float* yb = g_Y + (size_t)g_pp1[t] * DIM;
    float lsum = 0.f, lsq = 0.f;
    for (int d = tid; d < DIM; d += 256) {
        float v = p0 * ya[d] + p1 * yb[d];
        sv[d] = v;
        lsum += v; lsq += v * v;
    }
    lsum = warp_sum(lsum); lsq = warp_sum(lsq);
    int lane = tid & 31, wid = tid >> 5;
    if (lane == 0) { rs[wid] = lsum; rq[wid] = lsq; }
    __syncthreads();
    if (tid == 0) {
        float s = 0.f, q = 0.f;
#pragma unroll
        for (int w = 0; w < 8; w++) { s += rs[w]; q += rq[w]; }
        rs[0] = s; rq[0] = q;
    }
    __syncthreads();
    float mu  = rs[0] / DIM;
    float var = rq[0] / DIM - mu * mu;
    float inv = rsqrtf(var + EPS);
    float* outr = out + (size_t)t * DIM;
    for (int d = tid; d < DIM; d += 256)
        outr[d] = (sv[d] - mu) * inv * ln_g[d] + ln_b[d];
}

// ---------------- launch ----------------
extern "C" void kernel_launch(void* const* d_in, const int* in_sizes, int n_in,
                              void* d_out, int out_size) {
    const float* x      = (const float*)d_in[0];
    const float* gate_w = (const float*)d_in[1];
    const float* gate_b = (const float*)d_in[2];
    const float* w1     = (const float*)d_in[3];
    const float* b1     = (const float*)d_in[4];
    const float* w2     = (const float*)d_in[5];
    const float* b2     = (const float*)d_in[6];
    const float* ln_g   = (const float*)d_in[7];
    const float* ln_b   = (const float*)d_in[8];
    float* out = (float*)d_out;

    cudaFuncSetAttribute(ffn_mma_kernel<DIM, FF, true>,
                         cudaFuncAttributeMaxDynamicSharedMemorySize, SMEM_FFN);
    cudaFuncSetAttribute(ffn_mma_kernel<FF, DIM, false>,
                         cudaFuncAttributeMaxDynamicSharedMemorySize, SMEM_FFN);

    fused_gate_convw<<<GATE_BLOCKS + CONV_BLOCKS, 256>>>(x, gate_w, gate_b, w1, w2);
    prefix_kernel<<<1, 256>>>();
    scatter_kernel<<<N_TOK / 8, 256>>>(x);
    ffn_mma_kernel<DIM, FF, true ><<<dim3(FF / 128, 32, NE), 256, SMEM_FFN>>>(b1);
    ffn_mma_kernel<FF, DIM, false><<<dim3(DIM / 128, 32, NE), 256, SMEM_FFN>>>(b2);
    ln_kernel<<<N_TOK, 256>>>(ln_g, ln_b, out);
}

// round 15
// speedup vs baseline: 1.8336x; 1.0828x over previous
#include <cuda_runtime.h>
#include <cuda_fp16.h>
#include <cstdint>
#include <math.h>

// ---------------- problem constants ----------------
#define N_TOK 4096
#define DIM   1024
#define FF    4096
#define NE    8
#define TEMP  0.9f
#define EPS   1e-5f
#define PADMAX 9216
#define GATE_BLOCKS 512
#define CONV_BLOCKS 4096

// ---------------- static device scratch ----------------
__device__ __half g_Xe[(size_t)PADMAX * DIM];    // fp16 gathered X
__device__ __half g_H [(size_t)PADMAX * FF];     // fp16 gelu acts
__device__ float  g_Y [(size_t)PADMAX * DIM];    // fp32 expert outputs
__device__ __half g_w1h[(size_t)NE * DIM * FF];  // fp16 w1
__device__ __half g_w2h[(size_t)NE * FF * DIM];  // fp16 w2
__device__ int   g_e0[N_TOK], g_e1[N_TOK];
__device__ float g_p0[N_TOK], g_p1[N_TOK];
__device__ int   g_pp0[N_TOK], g_pp1[N_TOK];
__device__ int   g_counts[NE], g_poff[NE], g_cursor[NE];

// ---------------- helpers ----------------
__device__ __forceinline__ uint32_t smem_u32(const void* p) {
    uint32_t a;
    asm("{ .reg .u64 t; cvta.to.shared.u64 t, %1; cvt.u32.u64 %0, t; }" : "=r"(a) : "l"(p));
    return a;
}
__device__ __forceinline__ void cp_async16(uint32_t dst, const void* src) {
    asm volatile("cp.async.cg.shared.global [%0], [%1], 16;" :: "r"(dst), "l"(src));
}
__device__ __forceinline__ uint32_t pack_f16x2(float lo, float hi) {
    uint32_t d;
    asm("cvt.rn.f16x2.f32 %0, %1, %2;" : "=r"(d) : "f"(hi), "f"(lo));
    return d;
}
__device__ __forceinline__ void ldmx4(uint32_t* r, uint32_t addr) {
    asm volatile("ldmatrix.sync.aligned.m8n8.x4.shared.b16 {%0,%1,%2,%3}, [%4];"
        : "=r"(r[0]), "=r"(r[1]), "=r"(r[2]), "=r"(r[3]) : "r"(addr));
}
__device__ __forceinline__ void ldmx4_t(uint32_t* r, uint32_t addr) {
    asm volatile("ldmatrix.sync.aligned.m8n8.x4.trans.shared.b16 {%0,%1,%2,%3}, [%4];"
        : "=r"(r[0]), "=r"(r[1]), "=r"(r[2]), "=r"(r[3]) : "r"(addr));
}
__device__ __forceinline__ void mma_f16(float* c, const uint32_t* a, const uint32_t* b) {
    asm volatile(
        "mma.sync.aligned.m16n8k16.row.col.f32.f16.f16.f32 "
        "{%0,%1,%2,%3}, {%4,%5,%6,%7}, {%8,%9}, {%0,%1,%2,%3};"
        : "+f"(c[0]), "+f"(c[1]), "+f"(c[2]), "+f"(c[3])
        : "r"(a[0]), "r"(a[1]), "r"(a[2]), "r"(a[3]), "r"(b[0]), "r"(b[1]));
}
__device__ __forceinline__ float warp_sum(float v) {
#pragma unroll
    for (int o = 16; o > 0; o >>= 1) v += __shfl_xor_sync(0xffffffffu, v, o);
    return v;
}

// ---------------- fused gate + weight fp16 conversion ----------------
__global__ __launch_bounds__(256)
void fused_gate_convw(const float* __restrict__ x,
                      const float* __restrict__ gw,
                      const float* __restrict__ gb,
                      const float* __restrict__ w1,
                      const float* __restrict__ w2) {
    if (blockIdx.x < GATE_BLOCKS) {
        int warp = threadIdx.x >> 5, lane = threadIdx.x & 31;
        int t = blockIdx.x * 8 + warp;
        float acc[NE];
#pragma unroll
        for (int e = 0; e < NE; e++) acc[e] = 0.f;
        const float* xr = x + (size_t)t * DIM;
        for (int d = lane; d < DIM; d += 32) {
            float xv = xr[d];
            const float4* g4 = reinterpret_cast<const float4*>(gw + (size_t)d * NE);
            float4 a = g4[0], b = g4[1];
            acc[0] += xv * a.x; acc[1] += xv * a.y; acc[2] += xv * a.z; acc[3] += xv * a.w;
            acc[4] += xv * b.x; acc[5] += xv * b.y; acc[6] += xv * b.z; acc[7] += xv * b.w;
        }
#pragma unroll
        for (int e = 0; e < NE; e++) acc[e] = warp_sum(acc[e]);
        if (lane == 0) {
            float lg[NE];
#pragma unroll
            for (int e = 0; e < NE; e++) lg[e] = (acc[e] + gb[e]) / TEMP;
            int i0 = 0;
#pragma unroll
            for (int e = 1; e < NE; e++) if (lg[e] > lg[i0]) i0 = e;
            int i1 = (i0 == 0) ? 1 : 0;
#pragma unroll
            for (int e = 0; e < NE; e++)
                if (e != i0 && lg[e] > lg[i1]) i1 = e;
            float ev = expf(lg[i1] - lg[i0]);
            float s = 1.f + ev;
            g_e0[t] = i0; g_e1[t] = i1;
            g_p0[t] = 1.f / s; g_p1[t] = ev / s;
        }
    } else {
        const size_t total4 = (size_t)NE * DIM * FF / 4;
        size_t i = (size_t)(blockIdx.x - GATE_BLOCKS) * 256 + threadIdx.x;
        const float4* s1 = reinterpret_cast<const float4*>(w1);
        const float4* s2 = reinterpret_cast<const float4*>(w2);
        uint2* d1 = reinterpret_cast<uint2*>(g_w1h);
        uint2* d2 = reinterpret_cast<uint2*>(g_w2h);
        for (size_t j = i; j < total4; j += (size_t)CONV_BLOCKS * 256) {
            float4 v = s1[j];
            d1[j] = make_uint2(pack_f16x2(v.x, v.y), pack_f16x2(v.z, v.w));
            float4 u = s2[j];
            d2[j] = make_uint2(pack_f16x2(u.x, u.y), pack_f16x2(u.z, u.w));
        }
    }
}

// ---------------- prefix: histogram + offsets ----------------
__global__ void prefix_kernel() {
    __shared__ int h[NE];
    int tid = threadIdx.x;
    if (tid < NE) h[tid] = 0;
    __syncthreads();
    for (int t = tid; t < N_TOK; t += 256) {
        atomicAdd(&h[g_e0[t]], 1);
        atomicAdd(&h[g_e1[t]], 1);
    }
    __syncthreads();
    if (tid == 0) {
        int s = 0;
#pragma unroll
        for (int e = 0; e < NE; e++) {
            g_counts[e] = h[e];
            g_poff[e] = s;
            s += ((h[e] + 127) / 128) * 128;
            g_cursor[e] = 0;
        }
    }
}

// ---------------- scatter: fused assign + gather ----------------
__global__ __launch_bounds__(256)
void scatter_kernel(const float* __restrict__ x) {
    int warp = threadIdx.x >> 5, lane = threadIdx.x & 31;
    int t = blockIdx.x * 8 + warp;
    int e0 = g_e0[t], e1 = g_e1[t];
    int p = 0, q = 0;
    if (lane == 0) {
        p = g_poff[e0] + atomicAdd(&g_cursor[e0], 1);
        q = g_poff[e1] + atomicAdd(&g_cursor[e1], 1);
        g_pp0[t] = p; g_pp1[t] = q;
    }
    p = __shfl_sync(0xffffffffu, p, 0);
    q = __shfl_sync(0xffffffffu, q, 0);
    const float4* xr = reinterpret_cast<const float4*>(x + (size_t)t * DIM);
    uint2* oa = reinterpret_cast<uint2*>(g_Xe) + (size_t)p * (DIM / 4);
    uint2* ob = reinterpret_cast<uint2*>(g_Xe) + (size_t)q * (DIM / 4);
#pragma unroll
    for (int i = 0; i < DIM / 128; i++) {
        int idx = lane + 32 * i;
        float4 v = xr[idx];
        uint2 h = make_uint2(pack_f16x2(v.x, v.y), pack_f16x2(v.z, v.w));
        oa[idx] = h;
        ob[idx] = h;
    }
}

// ---------------- fp16 mma.sync GEMM (all-fp16 operands, ldmatrix) ----------------
// CTA tile 128x128, BK=64, 3-stage cp.async pipeline, occupancy 2.
// 256 threads = 8 warps (2m x 4n), warp tile 64 x 32, mma m16n8k16.
// One sync per K64 chunk: 64 MMAs between barriers.
#define STAGES 3
#define A_STRH 72                          // halfs: 64 + 8 pad
#define A_STGH (128 * A_STRH)              // 9216 halfs per stage
#define BSTRH_C 136                        // halfs: 128 + 8 pad
#define BSTGH_C (64 * BSTRH_C)             // 8704 halfs per stage
#define SMEM_FFN (STAGES * (A_STGH + BSTGH_C) * 2)   // 107520 B

template<int K, int NF, bool GELU>
__global__ __launch_bounds__(256, 2)
void ffn_mma_kernel(const float* __restrict__ bias_in) {
    constexpr int BN    = 128;
    constexpr int WN    = BN / 4;          // 32
    constexpr int NFR   = WN / 8;          // 4

    int e = blockIdx.z;
    int cnt = g_counts[e];
    int mt = blockIdx.y;
    if (mt * 128 >= cnt) return;
    int m0 = g_poff[e] + mt * 128;
    int n0 = blockIdx.x * BN;

    const __half* Abase = (GELU ? g_Xe : g_H) + (size_t)m0 * K;
    const __half* Bbase = (GELU ? g_w1h : g_w2h) + (size_t)e * K * NF + n0;
    const float*  bias  = bias_in + (size_t)e * NF + n0;

    extern __shared__ __half smh[];
    __half* Asm = smh;
    __half* Bsm = smh + STAGES * A_STGH;
    uint32_t sA32 = smem_u32(Asm), sB32 = smem_u32(Bsm);

    int tid = threadIdx.x, wid = tid >> 5, lane = tid & 31;
    int warp_m = wid & 1, warp_n = wid >> 1;
    int group = lane >> 2, tig = lane & 3;
    int rw = lane & 7, quad = lane >> 3;

    auto load_stage = [&](int kt, int s) {
        int k0 = kt * 64;
        uint32_t aD = sA32 + s * (A_STGH * 2);
        uint32_t bD = sB32 + s * (BSTGH_C * 2);
#pragma unroll
        for (int i = 0; i < 4; i++) {            // A: 128 rows x 8 x 16B
            int idx = tid + i * 256;
            int row = idx >> 3, c8 = idx & 7;
            cp_async16(aD + row * (A_STRH * 2) + c8 * 16,
                       Abase + (size_t)row * K + k0 + c8 * 8);
        }
#pragma unroll
        for (int i = 0; i < 4; i++) {            // B: 64 rows x 16 x 16B
            int idx = tid + i * 256;
            int kk = idx >> 4, c8 = idx & 15;
            cp_async16(bD + (kk * BSTRH_C + c8 * 8) * 2,
                       Bbase + (size_t)(k0 + kk) * NF + c8 * 8);
        }
        asm volatile("cp.async.commit_group;");
    };

    float acc[4][NFR][4];
#pragma unroll
    for (int i = 0; i < 4; i++)
#pragma unroll
        for (int j = 0; j < NFR; j++)
#pragma unroll
            for (int q = 0; q < 4; q++) acc[i][j][q] = 0.f;

    const int ktiles = K / 64;
    load_stage(0, 0);
    load_stage(1, 1);

    for (int kt = 0; kt < ktiles; kt++) {
        if (kt == ktiles - 1)
            asm volatile("cp.async.wait_group 0;" ::: "memory");
        else
            asm volatile("cp.async.wait_group 1;" ::: "memory");
        __syncthreads();

        if (kt + 2 < ktiles)
            load_stage(kt + 2, (kt + 2) % STAGES);

        int s = kt % STAGES;
        uint32_t aS = sA32 + s * (A_STGH * 2);
        uint32_t bS = sB32 + s * (BSTGH_C * 2);
#pragma unroll
        for (int ks = 0; ks < 4; ks++) {         // four k16 steps per K64 chunk
            int kb = ks * 16;
            uint32_t a[4][4], b[NFR][2];
#pragma unroll
            for (int m = 0; m < 4; m++) {
                int row = warp_m * 64 + m * 16 + rw + (quad & 1) * 8;
                int col = kb + (quad >> 1) * 8;
                ldmx4(a[m], aS + (row * A_STRH + col) * 2);
            }
#pragma unroll
            for (int n2 = 0; n2 < NFR / 2; n2++) {
                uint32_t r[4];
                int krow = kb + rw + (quad & 1) * 8;
                int col  = warp_n * WN + n2 * 16 + (quad >> 1) * 8;
                ldmx4_t(r, bS + (krow * BSTRH_C + col) * 2);
                b[2 * n2][0] = r[0]; b[2 * n2][1] = r[1];
                b[2 * n2 + 1][0] = r[2]; b[2 * n2 + 1][1] = r[3];
            }
#pragma unroll
            for (int m = 0; m < 4; m++)
#pragma unroll
                for (int n = 0; n < NFR; n++)
                    mma_f16(acc[m][n], a[m], b[n]);
        }
    }

    // epilogue: bias (+gelu); GEMM1 stores fp16 H, GEMM2 stores fp32 Y
#pragma unroll
    for (int m = 0; m < 4; m++) {
        int r0 = m0 + warp_m * 64 + m * 16 + group;
#pragma unroll
        for (int n = 0; n < NFR; n++) {
            int c = warp_n * WN + n * 8 + tig * 2;
            float bv0 = bias[c], bv1 = bias[c + 1];
#pragma unroll
            for (int h = 0; h < 2; h++) {
                float v0 = acc[m][n][h * 2 + 0] + bv0;
                float v1 = acc[m][n][h * 2 + 1] + bv1;
                if (GELU) {
                    v0 = 0.5f * v0 * (1.f + erff(v0 * 0.70710678118654752f));
                    v1 = 0.5f * v1 * (1.f + erff(v1 * 0.70710678118654752f));
                    *reinterpret_cast<uint32_t*>(
                        g_H + (size_t)(r0 + h * 8) * NF + n0 + c) = pack_f16x2(v0, v1);
                } else {
                    *reinterpret_cast<float2*>(
                        g_Y + (size_t)(r0 + h * 8) * NF + n0 + c) = make_float2(v0, v1);
                }
            }
        }
    }
}

// ---------------- combine + LayerNorm ----------------
__global__ void ln_kernel(const float* __restrict__ ln_g,
                          const float* __restrict__ ln_b,
                          float* __restrict__ out) {
    int t = blockIdx.x;
    __shared__ float sv[DIM];
    __shared__ float rs[8], rq[8];
    int tid = threadIdx.x;
    float p0 = g_p0[t], p1 = g_p1[t];
    const float* ya = g_Y + (size_t)g_pp0[t] * DIM;
    const float* yb = g_Y + (size_t)g_pp1[t] * DIM;
    float lsum = 0.f, lsq = 0.f;
    for (int d = tid; d < DIM; d += 256) {
        float v = p0 * ya[d] + p1 * yb[d];
        sv[d] = v;
        lsum += v; lsq += v * v;
    }
    lsum = warp_sum(lsum); lsq = warp_sum(lsq);
    int lane = tid & 31, wid = tid >> 5;
    if (lane == 0) { rs[wid] = lsum; rq[wid] = lsq; }
    __syncthreads();
    if (tid == 0) {
        float s = 0.f, q = 0.f;
#pragma unroll
        for (int w = 0; w < 8; w++) { s += rs[w]; q += rq[w]; }
        rs[0] = s; rq[0] = q;
    }
    __syncthreads();
    float mu  = rs[0] / DIM;
    float var = rq[0] / DIM - mu * mu;
    float inv = rsqrtf(var + EPS);
    float* outr = out + (size_t)t * DIM;
    for (int d = tid; d < DIM; d += 256)
        outr[d] = (sv[d] - mu) * inv * ln_g[d] + ln_b[d];
}

// ---------------- launch ----------------
extern "C" void kernel_launch(void* const* d_in, const int* in_sizes, int n_in,
                              void* d_out, int out_size) {
    const float* x      = (const float*)d_in[0];
    const float* gate_w = (const float*)d_in[1];
    const float* gate_b = (const float*)d_in[2];
    const float* w1     = (const float*)d_in[3];
    const float* b1     = (const float*)d_in[4];
    const float* w2     = (const float*)d_in[5];
    const float* b2     = (const float*)d_in[6];
    const float* ln_g   = (const float*)d_in[7];
    const float* ln_b   = (const float*)d_in[8];
    float* out = (float*)d_out;

    cudaFuncSetAttribute(ffn_mma_kernel<DIM, FF, true>,
                         cudaFuncAttributeMaxDynamicSharedMemorySize, SMEM_FFN);
    cudaFuncSetAttribute(ffn_mma_kernel<FF, DIM, false>,
                         cudaFuncAttributeMaxDynamicSharedMemorySize, SMEM_FFN);

    fused_gate_convw<<<GATE_BLOCKS + CONV_BLOCKS, 256>>>(x, gate_w, gate_b, w1, w2);
    prefix_kernel<<<1, 256>>>();
    scatter_kernel<<<N_TOK / 8, 256>>>(x);
    ffn_mma_kernel<DIM, FF, true ><<<dim3(FF / 128, 32, NE), 256, SMEM_FFN>>>(b1);
    ffn_mma_kernel<FF, DIM, false><<<dim3(DIM / 128, 32, NE), 256, SMEM_FFN>>>(b2);
    ln_kernel<<<N_TOK, 256>>>(ln_g, ln_b, out);
}

// round 16
// speedup vs baseline: 1.8595x; 1.0141x over previous
#include <cuda_runtime.h>
#include <cuda_fp16.h>
#include <cstdint>
#include <math.h>

// ---------------- problem constants ----------------
#define N_TOK 4096
#define DIM   1024
#define FF    4096
#define NE    8
#define TEMP  0.9f
#define EPS   1e-5f
#define PADMAX 9216
#define GATE_BLOCKS 512
#define CONV_BLOCKS 2048      // w1-only conversion blocks in pre-GEMM kernel
#define G1_CONV_X 8           // extra grid.x slots in GEMM1 for w2 conversion

// ---------------- static device scratch ----------------
__device__ __half g_Xe[(size_t)PADMAX * DIM];    // fp16 gathered X
__device__ __half g_H [(size_t)PADMAX * FF];     // fp16 gelu acts
__device__ float  g_Y [(size_t)PADMAX * DIM];    // fp32 expert outputs
__device__ __half g_w1h[(size_t)NE * DIM * FF];  // fp16 w1
__device__ __half g_w2h[(size_t)NE * FF * DIM];  // fp16 w2
__device__ int   g_e0[N_TOK], g_e1[N_TOK];
__device__ float g_p0[N_TOK], g_p1[N_TOK];
__device__ int   g_pp0[N_TOK], g_pp1[N_TOK];
__device__ int   g_counts[NE], g_poff[NE], g_cursor[NE];

// ---------------- helpers ----------------
__device__ __forceinline__ uint32_t smem_u32(const void* p) {
    uint32_t a;
    asm("{ .reg .u64 t; cvta.to.shared.u64 t, %1; cvt.u32.u64 %0, t; }" : "=r"(a) : "l"(p));
    return a;
}
__device__ __forceinline__ void cp_async16(uint32_t dst, const void* src) {
    asm volatile("cp.async.cg.shared.global [%0], [%1], 16;" :: "r"(dst), "l"(src));
}
__device__ __forceinline__ uint32_t pack_f16x2(float lo, float hi) {
    uint32_t d;
    asm("cvt.rn.f16x2.f32 %0, %1, %2;" : "=r"(d) : "f"(hi), "f"(lo));
    return d;
}
__device__ __forceinline__ void ldmx4(uint32_t* r, uint32_t addr) {
    asm volatile("ldmatrix.sync.aligned.m8n8.x4.shared.b16 {%0,%1,%2,%3}, [%4];"
        : "=r"(r[0]), "=r"(r[1]), "=r"(r[2]), "=r"(r[3]) : "r"(addr));
}
__device__ __forceinline__ void ldmx4_t(uint32_t* r, uint32_t addr) {
    asm volatile("ldmatrix.sync.aligned.m8n8.x4.trans.shared.b16 {%0,%1,%2,%3}, [%4];"
        : "=r"(r[0]), "=r"(r[1]), "=r"(r[2]), "=r"(r[3]) : "r"(addr));
}
__device__ __forceinline__ void mma_f16(float* c, const uint32_t* a, const uint32_t* b) {
    asm volatile(
        "mma.sync.aligned.m16n8k16.row.col.f32.f16.f16.f32 "
        "{%0,%1,%2,%3}, {%4,%5,%6,%7}, {%8,%9}, {%0,%1,%2,%3};"
        : "+f"(c[0]), "+f"(c[1]), "+f"(c[2]), "+f"(c[3])
        : "r"(a[0]), "r"(a[1]), "r"(a[2]), "r"(a[3]), "r"(b[0]), "r"(b[1]));
}
__device__ __forceinline__ float warp_sum(float v) {
#pragma unroll
    for (int o = 16; o > 0; o >>= 1) v += __shfl_xor_sync(0xffffffffu, v, o);
    return v;
}

// ---------------- fused gate + w1 fp16 conversion ----------------
__global__ __launch_bounds__(256)
void fused_gate_convw1(const float* __restrict__ x,
                       const float* __restrict__ gw,
                       const float* __restrict__ gb,
                       const float* __restrict__ w1) {
    if (blockIdx.x < GATE_BLOCKS) {
        int warp = threadIdx.x >> 5, lane = threadIdx.x & 31;
        int t = blockIdx.x * 8 + warp;
        float acc[NE];
#pragma unroll
        for (int e = 0; e < NE; e++) acc[e] = 0.f;
        const float* xr = x + (size_t)t * DIM;
        for (int d = lane; d < DIM; d += 32) {
            float xv = xr[d];
            const float4* g4 = reinterpret_cast<const float4*>(gw + (size_t)d * NE);
            float4 a = g4[0], b = g4[1];
            acc[0] += xv * a.x; acc[1] += xv * a.y; acc[2] += xv * a.z; acc[3] += xv * a.w;
            acc[4] += xv * b.x; acc[5] += xv * b.y; acc[6] += xv * b.z; acc[7] += xv * b.w;
        }
#pragma unroll
        for (int e = 0; e < NE; e++) acc[e] = warp_sum(acc[e]);
        if (lane == 0) {
            float lg[NE];
#pragma unroll
            for (int e = 0; e < NE; e++) lg[e] = (acc[e] + gb[e]) / TEMP;
            int i0 = 0;
#pragma unroll
            for (int e = 1; e < NE; e++) if (lg[e] > lg[i0]) i0 = e;
            int i1 = (i0 == 0) ? 1 : 0;
#pragma unroll
            for (int e = 0; e < NE; e++)
                if (e != i0 && lg[e] > lg[i1]) i1 = e;
            float ev = expf(lg[i1] - lg[i0]);
            float s = 1.f + ev;
            g_e0[t] = i0; g_e1[t] = i1;
            g_p0[t] = 1.f / s; g_p1[t] = ev / s;
        }
    } else {
        const size_t total4 = (size_t)NE * DIM * FF / 4;
        size_t i = (size_t)(blockIdx.x - GATE_BLOCKS) * 256 + threadIdx.x;
        const float4* s1 = reinterpret_cast<const float4*>(w1);
        uint2* d1 = reinterpret_cast<uint2*>(g_w1h);
        for (size_t j = i; j < total4; j += (size_t)CONV_BLOCKS * 256) {
            float4 v = s1[j];
            d1[j] = make_uint2(pack_f16x2(v.x, v.y), pack_f16x2(v.z, v.w));
        }
    }
}

// ---------------- prefix: histogram + offsets ----------------
__global__ void prefix_kernel() {
    __shared__ int h[NE];
    int tid = threadIdx.x;
    if (tid < NE) h[tid] = 0;
    __syncthreads();
    for (int t = tid; t < N_TOK; t += 256) {
        atomicAdd(&h[g_e0[t]], 1);
        atomicAdd(&h[g_e1[t]], 1);
    }
    __syncthreads();
    if (tid == 0) {
        int s = 0;
#pragma unroll
        for (int e = 0; e < NE; e++) {
            g_counts[e] = h[e];
            g_poff[e] = s;
            s += ((h[e] + 127) / 128) * 128;
            g_cursor[e] = 0;
        }
    }
}

// ---------------- scatter: fused assign + gather ----------------
__global__ __launch_bounds__(256)
void scatter_kernel(const float* __restrict__ x) {
    int warp = threadIdx.x >> 5, lane = threadIdx.x & 31;
    int t = blockIdx.x * 8 + warp;
    int e0 = g_e0[t], e1 = g_e1[t];
    int p = 0, q = 0;
    if (lane == 0) {
        p = g_poff[e0] + atomicAdd(&g_cursor[e0], 1);
        q = g_poff[e1] + atomicAdd(&g_cursor[e1], 1);
        g_pp0[t] = p; g_pp1[t] = q;
    }
    p = __shfl_sync(0xffffffffu, p, 0);
    q = __shfl_sync(0xffffffffu, q, 0);
    const float4* xr = reinterpret_cast<const float4*>(x + (size_t)t * DIM);
    uint2* oa = reinterpret_cast<uint2*>(g_Xe) + (size_t)p * (DIM / 4);
    uint2* ob = reinterpret_cast<uint2*>(g_Xe) + (size_t)q * (DIM / 4);
#pragma unroll
    for (int i = 0; i < DIM / 128; i++) {
        int idx = lane + 32 * i;
        float4 v = xr[idx];
        uint2 h = make_uint2(pack_f16x2(v.x, v.y), pack_f16x2(v.z, v.w));
        oa[idx] = h;
        ob[idx] = h;
    }
}

// ---------------- fp16 mma.sync GEMM (all-fp16 operands, ldmatrix) ----------------
// CTA tile 128x128, BK=64, 3-stage cp.async pipeline, occupancy 2.
// GEMM1 additionally carries w2->fp16 conversion blocks (blockIdx.x >= FF/128),
// hidden under GEMM1's compute (GEMM1 DRAM util is ~6%).
#define STAGES 3
#define A_STRH 72                          // halfs: 64 + 8 pad
#define A_STGH (128 * A_STRH)
#define BSTRH_C 136                        // halfs: 128 + 8 pad
#define BSTGH_C (64 * BSTRH_C)
#define SMEM_FFN (STAGES * (A_STGH + BSTGH_C) * 2)   // 107520 B

template<int K, int NF, bool GELU>
__global__ __launch_bounds__(256, 2)
void ffn_mma_kernel(const float* __restrict__ bias_in,
                    const float* __restrict__ w2_src) {
    constexpr int BN  = 128;
    constexpr int WN  = BN / 4;            // 32
    constexpr int NFR = WN / 8;            // 4
    constexpr int NXT = NF / 128;          // mma x-tiles

    if (GELU && blockIdx.x >= (unsigned)NXT) {
        // w2 fp16 conversion, spread over G1_CONV_X*32*NE blocks
        int cb = (blockIdx.x - NXT) + G1_CONV_X * (blockIdx.y + 32 * blockIdx.z);
        const size_t total4 = (size_t)NE * FF * DIM / 4;
        size_t i = (size_t)cb * 256 + threadIdx.x;
        const float4* s2 = reinterpret_cast<const float4*>(w2_src);
        uint2* d2 = reinterpret_cast<uint2*>(g_w2h);
        const size_t step = (size_t)G1_CONV_X * 32 * NE * 256;
        for (size_t j = i; j < total4; j += step) {
            float4 u = s2[j];
            d2[j] = make_uint2(pack_f16x2(u.x, u.y), pack_f16x2(u.z, u.w));
        }
        return;
    }

    int e = blockIdx.z;
    int cnt = g_counts[e];
    int mt = blockIdx.y;
    if (mt * 128 >= cnt) return;
    int m0 = g_poff[e] + mt * 128;
    int n0 = blockIdx.x * BN;

    const __half* Abase = (GELU ? g_Xe : g_H) + (size_t)m0 * K;
    const __half* Bbase = (GELU ? g_w1h : g_w2h) + (size_t)e * K * NF + n0;
    const float*  bias  = bias_in + (size_t)e * NF + n0;

    extern __shared__ __half smh[];
    __half* Asm = smh;
    __half* Bsm = smh + STAGES * A_STGH;
    uint32_t sA32 = smem_u32(Asm), sB32 = smem_u32(Bsm);

    int tid = threadIdx.x, wid = tid >> 5, lane = tid & 31;
    int warp_m = wid & 1, warp_n = wid >> 1;
    int group = lane >> 2, tig = lane & 3;
    int rw = lane & 7, quad = lane >> 3;

    auto load_stage = [&](int kt, int s) {
        int k0 = kt * 64;
        uint32_t aD = sA32 + s * (A_STGH * 2);
        uint32_t bD = sB32 + s * (BSTGH_C * 2);
#pragma unroll
        for (int i = 0; i < 4; i++) {            // A: 128 rows x 8 x 16B
            int idx = tid + i * 256;
            int row = idx >> 3, c8 = idx & 7;
            cp_async16(aD + row * (A_STRH * 2) + c8 * 16,
                       Abase + (size_t)row * K + k0 + c8 * 8);
        }
#pragma unroll
        for (int i = 0; i < 4; i++) {            // B: 64 rows x 16 x 16B
            int idx = tid + i * 256;
            int kk = idx >> 4, c8 = idx & 15;
            cp_async16(bD + (kk * BSTRH_C + c8 * 8) * 2,
                       Bbase + (size_t)(k0 + kk) * NF + c8 * 8);
        }
        asm volatile("cp.async.commit_group;");
    };

    float acc[4][NFR][4];
#pragma unroll
    for (int i = 0; i < 4; i++)
#pragma unroll
        for (int j = 0; j < NFR; j++)
#pragma unroll
            for (int q = 0; q < 4; q++) acc[i][j][q] = 0.f;

    const int ktiles = K / 64;
    load_stage(0, 0);
    load_stage(1, 1);

    for (int kt = 0; kt < ktiles; kt++) {
        if (kt == ktiles - 1)
            asm volatile("cp.async.wait_group 0;" ::: "memory");
        else
            asm volatile("cp.async.wait_group 1;" ::: "memory");
        __syncthreads();

        if (kt + 2 < ktiles)
            load_stage(kt + 2, (kt + 2) % STAGES);

        int s = kt % STAGES;
        uint32_t aS = sA32 + s * (A_STGH * 2);
        uint32_t bS = sB32 + s * (BSTGH_C * 2);
#pragma unroll
        for (int ks = 0; ks < 4; ks++) {         // four k16 steps per K64 chunk
            int kb = ks * 16;
            uint32_t a[4][4], b[NFR][2];
#pragma unroll
            for (int m = 0; m < 4; m++) {
                int row = warp_m * 64 + m * 16 + rw + (quad & 1) * 8;
                int col = kb + (quad >> 1) * 8;
                ldmx4(a[m], aS + (row * A_STRH + col) * 2);
            }
#pragma unroll
            for (int n2 = 0; n2 < NFR / 2; n2++) {
                uint32_t r[4];
                int krow = kb + rw + (quad & 1) * 8;
                int col  = warp_n * WN + n2 * 16 + (quad >> 1) * 8;
                ldmx4_t(r, bS + (krow * BSTRH_C + col) * 2);
                b[2 * n2][0] = r[0]; b[2 * n2][1] = r[1];
                b[2 * n2 + 1][0] = r[2]; b[2 * n2 + 1][1] = r[3];
            }
#pragma unroll
            for (int m = 0; m < 4; m++)
#pragma unroll
                for (int n = 0; n < NFR; n++)
                    mma_f16(acc[m][n], a[m], b[n]);
        }
    }

    // epilogue: bias (+gelu); GEMM1 stores fp16 H, GEMM2 stores fp32 Y
#pragma unroll
    for (int m = 0; m < 4; m++) {
        int r0 = m0 + warp_m * 64 + m * 16 + group;
#pragma unroll
        for (int n = 0; n < NFR; n++) {
            int c = warp_n * WN + n * 8 + tig * 2;
            float bv0 = bias[c], bv1 = bias[c + 1];
#pragma unroll
            for (int h = 0; h < 2; h++) {
                float v0 = acc[m][n][h * 2 + 0] + bv0;
                float v1 = acc[m][n][h * 2 + 1] + bv1;
                if (GELU) {
                    v0 = 0.5f * v0 * (1.f + erff(v0 * 0.70710678118654752f));
                    v1 = 0.5f * v1 * (1.f + erff(v1 * 0.70710678118654752f));
                    *reinterpret_cast<uint32_t*>(
                        g_H + (size_t)(r0 + h * 8) * NF + n0 + c) = pack_f16x2(v0, v1);
                } else {
                    *reinterpret_cast<float2*>(
                        g_Y + (size_t)(r0 + h * 8) * NF + n0 + c) = make_float2(v0, v1);
                }
            }
        }
    }
}

// ---------------- combine + LayerNorm ----------------
__global__ void ln_kernel(const float* __restrict__ ln_g,
                          const float* __restrict__ ln_b,
                          float* __restrict__ out) {
    int t = blockIdx.x;
    __shared__ float sv[DIM];
    __shared__ float rs[8], rq[8];
    int tid = threadIdx.x;
    float p0 = g_p0[t], p1 = g_p1[t];
    const float* ya = g_Y + (size_t)g_pp0[t] * DIM;
    const float* yb = g_Y + (size_t)g_pp1[t] * DIM;
    float lsum = 0.f, lsq = 0.f;
    for (int d = tid; d < DIM; d += 256) {
        float v = p0 * ya[d] + p1 * yb[d];
        sv[d] = v;
        lsum += v; lsq += v * v;
    }
    lsum = warp_sum(lsum); lsq = warp_sum(lsq);
    int lane = tid & 31, wid = tid >> 5;
    if (lane == 0) { rs[wid] = lsum; rq[wid] = lsq; }
    __syncthreads();
    if (tid == 0) {
        float s = 0.f, q = 0.f;
#pragma unroll
        for (int w = 0; w < 8; w++) { s += rs[w]; q += rq[w]; }
        rs[0] = s; rq[0] = q;
    }
    __syncthreads();
    float mu  = rs[0] / DIM;
    float var = rq[0] / DIM - mu * mu;
    float inv = rsqrtf(var + EPS);
    float* outr = out + (size_t)t * DIM;
    for (int d = tid; d < DIM; d += 256)
        outr[d] = (sv[d] - mu) * inv * ln_g[d] + ln_b[d];
}

// ---------------- launch ----------------
extern "C" void kernel_launch(void* const* d_in, const int* in_sizes, int n_in,
                              void* d_out, int out_size) {
    const float* x      = (const float*)d_in[0];
    const float* gate_w = (const float*)d_in[1];
    const float* gate_b = (const float*)d_in[2];
    const float* w1     = (const float*)d_in[3];
    const float* b1     = (const float*)d_in[4];
    const float* w2     = (const float*)d_in[5];
    const float* b2     = (const float*)d_in[6];
    const float* ln_g   = (const float*)d_in[7];
    const float* ln_b   = (const float*)d_in[8];
    float* out = (float*)d_out;

    cudaFuncSetAttribute(ffn_mma_kernel<DIM, FF, true>,
                         cudaFuncAttributeMaxDynamicSharedMemorySize, SMEM_FFN);
    cudaFuncSetAttribute(ffn_mma_kernel<FF, DIM, false>,
                         cudaFuncAttributeMaxDynamicSharedMemorySize, SMEM_FFN);

    fused_gate_convw1<<<GATE_BLOCKS + CONV_BLOCKS, 256>>>(x, gate_w, gate_b, w1);
    prefix_kernel<<<1, 256>>>();
    scatter_kernel<<<N_TOK / 8, 256>>>(x);
    // GEMM1 carries w2 conversion in its extra grid.x slots
    ffn_mma_kernel<DIM, FF, true ><<<dim3(FF / 128 + G1_CONV_X, 32, NE), 256, SMEM_FFN>>>(b1, w2);
    ffn_mma_kernel<FF, DIM, false><<<dim3(DIM / 128, 32, NE), 256, SMEM_FFN>>>(b2, nullptr);
    ln_kernel<<<N_TOK, 256>>>(ln_g, ln_b, out);
}